// round 2
// baseline (speedup 1.0000x reference)
#include <cuda_runtime.h>
#include <cstdint>

#define HEAD_DIM 64
#define EMB_DIM 1024
#define BATCH 4
#define SEQ 4096
#define MTOT (BATCH*SEQ)

// Pre-rounded tf32 scratch. Q,K: [m][64] with column pairs (c, c+4) interleaved
// within each 8-group. V: transposed [b][dim][s] with key pairs interleaved.
__device__ float g_Q[(size_t)MTOT * 64];
__device__ float g_K[(size_t)MTOT * 64];
__device__ float g_VT[(size_t)BATCH * 64 * SEQ];
__device__ float g_Wt[3 * 64 * 1024];   // [mat][n][k] transposed, k pair-permuted, tf32

__device__ __forceinline__ float f2tf(float f) {
    uint32_t r; asm("cvt.rna.tf32.f32 %0, %1;" : "=r"(r) : "f"(f));
    return __uint_as_float(r);
}
__device__ __forceinline__ uint32_t fu(float f) { return __float_as_uint(f); }

__device__ __forceinline__ void mma8(float* c, const uint32_t* a, uint32_t b0, uint32_t b1) {
    asm volatile(
        "mma.sync.aligned.m16n8k8.row.col.f32.tf32.tf32.f32 "
        "{%0,%1,%2,%3}, {%4,%5,%6,%7}, {%8,%9}, {%0,%1,%2,%3};"
        : "+f"(c[0]), "+f"(c[1]), "+f"(c[2]), "+f"(c[3])
        : "r"(a[0]), "r"(a[1]), "r"(a[2]), "r"(a[3]), "r"(b0), "r"(b1));
}

__device__ __forceinline__ void cp16(uint32_t dst, const void* src) {
    asm volatile("cp.async.cg.shared.global [%0], [%1], 16;" :: "r"(dst), "l"(src));
}
#define CP_COMMIT() asm volatile("cp.async.commit_group;")
#define CP_WAIT1()  asm volatile("cp.async.wait_group 1;")
#define CP_WAIT0()  asm volatile("cp.async.wait_group 0;")

// pair-permutation within an 8-group: logical j -> 2*(j&3) + (j>>2)
__device__ __forceinline__ int perm8(int j) { return 2 * (j & 3) + (j >> 2); }

// ---------------------------------------------------------------------------
// Kernel 0: round W to tf32, transpose to [n][k], permute k pairs. 768 KB.
// ---------------------------------------------------------------------------
__global__ void w_prep_kernel(const float* __restrict__ Wq,
                              const float* __restrict__ Wk,
                              const float* __restrict__ Wv) {
    __shared__ float ts[64][65];
    const float* W = (blockIdx.y == 0) ? Wq : (blockIdx.y == 1) ? Wk : Wv;
    const int kt = blockIdx.x;      // 16 tiles of 64 k-rows
    const int t = threadIdx.x;      // 256 threads
#pragma unroll
    for (int i = 0; i < 16; i++) {
        int idx = i * 256 + t, r = idx >> 6, c = idx & 63;
        ts[r][c] = f2tf(W[(size_t)(kt * 64 + r) * 64 + c]);
    }
    __syncthreads();
    float* out = g_Wt + (size_t)blockIdx.y * 64 * 1024;
#pragma unroll
    for (int i = 0; i < 16; i++) {
        int idx = i * 256 + t, n = idx >> 6, r = idx & 63;
        int rp = (r & ~7) | perm8(r & 7);
        out[(size_t)n * 1024 + kt * 64 + rp] = ts[r][n];
    }
}

// ---------------------------------------------------------------------------
// Kernel 1: fused QKV projection. x read ONCE. cp.async double-buffered.
// Writes pre-rounded (and Q pre-scaled) tensors in attention-friendly layouts.
// ---------------------------------------------------------------------------
#define XS 20
#define WS 24
__global__ __launch_bounds__(128, 3) void qkv_proj_kernel(const float* __restrict__ x)
{
    __shared__ float xs[2][64 * XS];     // raw fp32 x tiles
    __shared__ float ws[2][192 * WS];    // tf32 W^T tiles (3 mats x 64 n-rows x 16 k)
    const int t = threadIdx.x, warp = t >> 5, lane = t & 31;
    const int lr4 = lane >> 2, cq = lane & 3;
    const int m0 = blockIdx.x * 64, rl = warp * 16 + lr4;
    const uint32_t xs_b = (uint32_t)__cvta_generic_to_shared(&xs[0][0]);
    const uint32_t ws_b = (uint32_t)__cvta_generic_to_shared(&ws[0][0]);

    float acc[3][8][4];
#pragma unroll
    for (int m = 0; m < 3; m++)
#pragma unroll
        for (int n = 0; n < 8; n++) {
            acc[m][n][0] = acc[m][n][1] = acc[m][n][2] = acc[m][n][3] = 0.f;
        }

    auto issue = [&](int kc, int st) {
#pragma unroll
        for (int i = 0; i < 2; i++) {   // x tile: 64 rows x 64B
            int c = i * 128 + t, r = c >> 2, ch = c & 3;
            cp16(xs_b + (uint32_t)(st * 64 * XS + r * XS + ch * 4) * 4,
                 x + (size_t)(m0 + r) * EMB_DIM + kc * 16 + ch * 4);
        }
#pragma unroll
        for (int i = 0; i < 6; i++) {   // W tiles: 192 rows x 64B
            int c = i * 128 + t, row = c >> 2, ch = c & 3;
            cp16(ws_b + (uint32_t)(st * 192 * WS + row * WS + ch * 4) * 4,
                 g_Wt + (size_t)row * 1024 + kc * 16 + ch * 4);
        }
        CP_COMMIT();
    };

    issue(0, 0);
    for (int kc = 0; kc < 64; kc++) {
        const int st = kc & 1;
        if (kc < 63) { issue(kc + 1, st ^ 1); CP_WAIT1(); } else { CP_WAIT0(); }
        __syncthreads();

        uint32_t a[2][4];
#pragma unroll
        for (int kk = 0; kk < 2; kk++) {
            a[kk][0] = fu(f2tf(xs[st][rl * XS + kk * 8 + cq]));
            a[kk][1] = fu(f2tf(xs[st][(rl + 8) * XS + kk * 8 + cq]));
            a[kk][2] = fu(f2tf(xs[st][rl * XS + kk * 8 + cq + 4]));
            a[kk][3] = fu(f2tf(xs[st][(rl + 8) * XS + kk * 8 + cq + 4]));
        }
#pragma unroll
        for (int m = 0; m < 3; m++)
#pragma unroll
            for (int n = 0; n < 8; n++)
#pragma unroll
                for (int kk = 0; kk < 2; kk++) {
                    float2 b = *reinterpret_cast<float2*>(
                        &ws[st][(m * 64 + n * 8 + lr4) * WS + kk * 8 + 2 * cq]);
                    mma8(acc[m][n], a[kk], fu(b.x), fu(b.y));
                }
        __syncthreads();
    }

    // Epilogue: Q (scaled), K -> [m][col_perm]; V -> transposed [b][dim][s_perm]
    const int mg0 = m0 + rl, mg1 = m0 + rl + 8;
    const size_t r0 = (size_t)mg0 * 64, r1 = (size_t)mg1 * 64;
    const int bb = mg0 >> 12;
    const int s0 = mg0 & 4095, s1 = mg1 & 4095;
    const int sp0 = (s0 & ~7) | perm8(s0 & 7);
    const int sp1 = (s1 & ~7) | perm8(s1 & 7);
    const int j0 = 2 * cq, j1 = 2 * cq + 1;
#pragma unroll
    for (int n = 0; n < 8; n++) {
        const int p0 = n * 8 + perm8(j0);
        const int p1 = n * 8 + perm8(j1);
        g_Q[r0 + p0] = f2tf(acc[0][n][0] * 0.125f);
        g_Q[r0 + p1] = f2tf(acc[0][n][1] * 0.125f);
        g_Q[r1 + p0] = f2tf(acc[0][n][2] * 0.125f);
        g_Q[r1 + p1] = f2tf(acc[0][n][3] * 0.125f);
        g_K[r0 + p0] = f2tf(acc[1][n][0]);
        g_K[r0 + p1] = f2tf(acc[1][n][1]);
        g_K[r1 + p0] = f2tf(acc[1][n][2]);
        g_K[r1 + p1] = f2tf(acc[1][n][3]);
        const int c0 = n * 8 + 2 * cq, c1 = c0 + 1;
        g_VT[((size_t)bb * 64 + c0) * SEQ + sp0] = f2tf(acc[2][n][0]);
        g_VT[((size_t)bb * 64 + c1) * SEQ + sp0] = f2tf(acc[2][n][1]);
        g_VT[((size_t)bb * 64 + c0) * SEQ + sp1] = f2tf(acc[2][n][2]);
        g_VT[((size_t)bb * 64 + c1) * SEQ + sp1] = f2tf(acc[2][n][3]);
    }
}

// ---------------------------------------------------------------------------
// Kernel 2: causal flash attention. cp.async double-buffered K/V, zero cvt,
// all B-fragments via single LDS.64 (pair-permuted layouts, stride 72 words).
// ---------------------------------------------------------------------------
#define KVS 72
#define ATTN_SMEM (2 * 2 * 64 * KVS * 4)
__global__ __launch_bounds__(128, 3) void attn_kernel(float* __restrict__ out)
{
    extern __shared__ float sm[];
    const int t = threadIdx.x, warp = t >> 5, lane = t & 31;
    const int lr4 = lane >> 2, cq = lane & 3;
    const int b = blockIdx.y, qi = blockIdx.x;
    const int q0 = qi * 64;
    const int rl = warp * 16 + lr4;
    const uint32_t sm_b = (uint32_t)__cvta_generic_to_shared(sm);

    // Q fragments directly from gmem (already tf32, scaled, pair-permuted)
    uint32_t aq[8][4];
    {
        const float* Qr0 = g_Q + (size_t)(b * SEQ + q0 + rl) * 64;
        const float* Qr1 = Qr0 + 8 * 64;
#pragma unroll
        for (int kk = 0; kk < 8; kk++) {
            float2 v0 = *reinterpret_cast<const float2*>(Qr0 + kk * 8 + 2 * cq);
            float2 v1 = *reinterpret_cast<const float2*>(Qr1 + kk * 8 + 2 * cq);
            aq[kk][0] = fu(v0.x); aq[kk][2] = fu(v0.y);
            aq[kk][1] = fu(v1.x); aq[kk][3] = fu(v1.y);
        }
    }

    auto issue = [&](int j, int st) {
        const float* Kg = g_K + ((size_t)b * SEQ + j * 64) * 64;
        const float* Vg = g_VT + (size_t)b * 64 * SEQ + j * 64;
        const uint32_t kb = sm_b + (uint32_t)st * 2 * 64 * KVS * 4;
        const uint32_t vb = kb + 64 * KVS * 4;
#pragma unroll
        for (int i = 0; i < 8; i++) {
            int c = i * 128 + t, r = c >> 4, ch = c & 15;
            cp16(kb + (uint32_t)(r * KVS + ch * 4) * 4, Kg + r * 64 + ch * 4);
        }
#pragma unroll
        for (int i = 0; i < 8; i++) {
            int c = i * 128 + t, r = c >> 4, ch = c & 15;
            cp16(vb + (uint32_t)(r * KVS + ch * 4) * 4, Vg + (size_t)r * SEQ + ch * 4);
        }
        CP_COMMIT();
    };

    float m0 = -1e30f, m1 = -1e30f, l0 = 0.f, l1 = 0.f;
    float o[8][4];
#pragma unroll
    for (int n = 0; n < 8; n++) { o[n][0] = o[n][1] = o[n][2] = o[n][3] = 0.f; }

    issue(0, 0);
    for (int j = 0; j <= qi; j++) {
        const int st = j & 1;
        if (j < qi) { issue(j + 1, st ^ 1); CP_WAIT1(); } else { CP_WAIT0(); }
        __syncthreads();
        const float* ks = sm + st * 2 * 64 * KVS;
        const float* vs = ks + 64 * KVS;

        // S = Q @ K^T
        float s[8][4];
#pragma unroll
        for (int n = 0; n < 8; n++) { s[n][0] = s[n][1] = s[n][2] = s[n][3] = 0.f; }
#pragma unroll
        for (int n = 0; n < 8; n++)
#pragma unroll
            for (int kk = 0; kk < 8; kk++) {
                float2 bb = *reinterpret_cast<const float2*>(
                    &ks[(n * 8 + lr4) * KVS + kk * 8 + 2 * cq]);
                mma8(s[n], aq[kk], fu(bb.x), fu(bb.y));
            }

        if (j == qi) {   // causal mask on diagonal tile
#pragma unroll
            for (int n = 0; n < 8; n++) {
                int c0 = n * 8 + 2 * cq;
                if (c0     > rl)     s[n][0] = -1e30f;
                if (c0 + 1 > rl)     s[n][1] = -1e30f;
                if (c0     > rl + 8) s[n][2] = -1e30f;
                if (c0 + 1 > rl + 8) s[n][3] = -1e30f;
            }
        }

        // online softmax
        float nm0 = m0, nm1 = m1;
#pragma unroll
        for (int n = 0; n < 8; n++) {
            nm0 = fmaxf(nm0, fmaxf(s[n][0], s[n][1]));
            nm1 = fmaxf(nm1, fmaxf(s[n][2], s[n][3]));
        }
        nm0 = fmaxf(nm0, __shfl_xor_sync(0xffffffffu, nm0, 1));
        nm0 = fmaxf(nm0, __shfl_xor_sync(0xffffffffu, nm0, 2));
        nm1 = fmaxf(nm1, __shfl_xor_sync(0xffffffffu, nm1, 1));
        nm1 = fmaxf(nm1, __shfl_xor_sync(0xffffffffu, nm1, 2));
        float sc0 = __expf(m0 - nm0), sc1 = __expf(m1 - nm1);
        m0 = nm0; m1 = nm1;

        float sum0 = 0.f, sum1 = 0.f;
#pragma unroll
        for (int n = 0; n < 8; n++) {
            float p0 = __expf(s[n][0] - nm0);
            float p1 = __expf(s[n][1] - nm0);
            float p2 = __expf(s[n][2] - nm1);
            float p3 = __expf(s[n][3] - nm1);
            sum0 += p0 + p1; sum1 += p2 + p3;
            s[n][0] = f2tf(p0); s[n][1] = f2tf(p1);
            s[n][2] = f2tf(p2); s[n][3] = f2tf(p3);
        }
        sum0 += __shfl_xor_sync(0xffffffffu, sum0, 1);
        sum0 += __shfl_xor_sync(0xffffffffu, sum0, 2);
        sum1 += __shfl_xor_sync(0xffffffffu, sum1, 1);
        sum1 += __shfl_xor_sync(0xffffffffu, sum1, 2);
        l0 = l0 * sc0 + sum0;
        l1 = l1 * sc1 + sum1;
#pragma unroll
        for (int n = 0; n < 8; n++) {
            o[n][0] *= sc0; o[n][1] *= sc0; o[n][2] *= sc1; o[n][3] *= sc1;
        }

        // O += P @ V (P accum layout -> A fragment via quad shuffles)
        const int src0 = (lane & 28) | (cq >> 1);
        const int src1 = src0 + 2;
        const bool odd = (cq & 1);
#pragma unroll
        for (int tt = 0; tt < 8; tt++) {
            float v00 = __shfl_sync(0xffffffffu, s[tt][0], src0);
            float v01 = __shfl_sync(0xffffffffu, s[tt][1], src0);
            float w00 = __shfl_sync(0xffffffffu, s[tt][2], src0);
            float w01 = __shfl_sync(0xffffffffu, s[tt][3], src0);
            float v10 = __shfl_sync(0xffffffffu, s[tt][0], src1);
            float v11 = __shfl_sync(0xffffffffu, s[tt][1], src1);
            float w10 = __shfl_sync(0xffffffffu, s[tt][2], src1);
            float w11 = __shfl_sync(0xffffffffu, s[tt][3], src1);
            uint32_t a[4];
            a[0] = fu(odd ? v01 : v00);
            a[1] = fu(odd ? w01 : w00);
            a[2] = fu(odd ? v11 : v10);
            a[3] = fu(odd ? w11 : w10);
#pragma unroll
            for (int n = 0; n < 8; n++) {
                float2 bb = *reinterpret_cast<const float2*>(
                    &vs[(n * 8 + lr4) * KVS + tt * 8 + 2 * cq]);
                mma8(o[n], a, fu(bb.x), fu(bb.y));
            }
        }
        __syncthreads();
    }

    const float i0 = 1.f / l0, i1 = 1.f / l1;
    float* Og = out + ((size_t)b * SEQ + q0) * HEAD_DIM;
#pragma unroll
    for (int n = 0; n < 8; n++) {
        int c = n * 8 + 2 * cq;
        *reinterpret_cast<float2*>(Og + rl * HEAD_DIM + c) =
            make_float2(o[n][0] * i0, o[n][1] * i0);
        *reinterpret_cast<float2*>(Og + (rl + 8) * HEAD_DIM + c) =
            make_float2(o[n][2] * i1, o[n][3] * i1);
    }
}

extern "C" void kernel_launch(void* const* d_in, const int* in_sizes, int n_in,
                              void* d_out, int out_size) {
    const float* x  = (const float*)d_in[0];
    const float* Wq = (const float*)d_in[1];
    const float* Wk = (const float*)d_in[2];
    const float* Wv = (const float*)d_in[3];
    float* out = (float*)d_out;

    w_prep_kernel<<<dim3(16, 3), 256>>>(Wq, Wk, Wv);
    qkv_proj_kernel<<<MTOT / 64, 128>>>(x);
    cudaFuncSetAttribute(attn_kernel, cudaFuncAttributeMaxDynamicSharedMemorySize, ATTN_SMEM);
    attn_kernel<<<dim3(SEQ / 64, BATCH), 128, ATTN_SMEM>>>(out);
}

// round 4
// speedup vs baseline: 1.1791x; 1.1791x over previous
#include <cuda_runtime.h>
#include <cstdint>

#define HEAD_DIM 64
#define EMB_DIM 1024
#define BATCH 4
#define SEQ 4096
#define MTOT (BATCH*SEQ)

// Pre-rounded tf32 scratch. Q,K: [m][64] col pairs (c, c+4) interleaved per
// 8-group. V: transposed [b][dim][s] with key pairs interleaved.
__device__ float g_Q[(size_t)MTOT * 64];
__device__ float g_K[(size_t)MTOT * 64];
__device__ float g_VT[(size_t)BATCH * 64 * SEQ];
__device__ float g_Wt[3 * 64 * 1024];   // [mat][n][k] transposed, pair-permuted, tf32

// split-KV partial scratch: slot = ((b*64 + qtile)*4 + chunk)
__device__ float g_po[(size_t)4 * 64 * 4 * 64 * 64];  // [slot][row64][col64]
__device__ float g_pm[4 * 64 * 4 * 64];
__device__ float g_pl[4 * 64 * 4 * 64];

__device__ __forceinline__ float f2tf(float f) {
    uint32_t r; asm("cvt.rna.tf32.f32 %0, %1;" : "=r"(r) : "f"(f));
    return __uint_as_float(r);
}
__device__ __forceinline__ uint32_t fu(float f) { return __float_as_uint(f); }

__device__ __forceinline__ void mma8(float* c, const uint32_t* a, uint32_t b0, uint32_t b1) {
    asm volatile(
        "mma.sync.aligned.m16n8k8.row.col.f32.tf32.tf32.f32 "
        "{%0,%1,%2,%3}, {%4,%5,%6,%7}, {%8,%9}, {%0,%1,%2,%3};"
        : "+f"(c[0]), "+f"(c[1]), "+f"(c[2]), "+f"(c[3])
        : "r"(a[0]), "r"(a[1]), "r"(a[2]), "r"(a[3]), "r"(b0), "r"(b1));
}

__device__ __forceinline__ void cp16(uint32_t dst, const void* src) {
    asm volatile("cp.async.cg.shared.global [%0], [%1], 16;" :: "r"(dst), "l"(src));
}
#define CP_COMMIT() asm volatile("cp.async.commit_group;")
#define CP_WAIT1()  asm volatile("cp.async.wait_group 1;")
#define CP_WAIT0()  asm volatile("cp.async.wait_group 0;")

__device__ __forceinline__ int perm8(int j) { return 2 * (j & 3) + (j >> 2); }

// ---------------------------------------------------------------------------
// Kernel 0: round W to tf32, transpose to [n][k], permute k pairs.
// ---------------------------------------------------------------------------
__global__ void w_prep_kernel(const float* __restrict__ Wq,
                              const float* __restrict__ Wk,
                              const float* __restrict__ Wv) {
    __shared__ float ts[64][65];
    const float* W = (blockIdx.y == 0) ? Wq : (blockIdx.y == 1) ? Wk : Wv;
    const int kt = blockIdx.x;
    const int t = threadIdx.x;   // 256 threads
    {
        // 64 rows x 4 chunks of 16 cols = 256 items, exactly one pass
        int r = t >> 2, c4 = (t & 3) * 16;
        const float* src = W + (size_t)(kt * 64 + r) * 64 + c4;
        const float4 v0 = *reinterpret_cast<const float4*>(src);
        const float4 v1 = *reinterpret_cast<const float4*>(src + 4);
        const float4 v2 = *reinterpret_cast<const float4*>(src + 8);
        const float4 v3 = *reinterpret_cast<const float4*>(src + 12);
        ts[r][c4+0]=f2tf(v0.x); ts[r][c4+1]=f2tf(v0.y); ts[r][c4+2]=f2tf(v0.z); ts[r][c4+3]=f2tf(v0.w);
        ts[r][c4+4]=f2tf(v1.x); ts[r][c4+5]=f2tf(v1.y); ts[r][c4+6]=f2tf(v1.z); ts[r][c4+7]=f2tf(v1.w);
        ts[r][c4+8]=f2tf(v2.x); ts[r][c4+9]=f2tf(v2.y); ts[r][c4+10]=f2tf(v2.z); ts[r][c4+11]=f2tf(v2.w);
        ts[r][c4+12]=f2tf(v3.x); ts[r][c4+13]=f2tf(v3.y); ts[r][c4+14]=f2tf(v3.z); ts[r][c4+15]=f2tf(v3.w);
    }
    __syncthreads();
    float* out = g_Wt + (size_t)blockIdx.y * 64 * 1024;
#pragma unroll
    for (int i = 0; i < 16; i++) {
        int idx = i * 256 + t, n = idx >> 6, r = idx & 63;
        int rp = (r & ~7) | perm8(r & 7);
        out[(size_t)n * 1024 + kt * 64 + rp] = ts[r][n];
    }
}

// ---------------------------------------------------------------------------
// Kernel 1: fused QKV projection, cp.async double-buffered, coalesced
// epilogues via smem transpose staging.
// ---------------------------------------------------------------------------
#define XS 20
#define WS 24
__global__ __launch_bounds__(128, 3) void qkv_proj_kernel(const float* __restrict__ x)
{
    __shared__ float xs[2][64 * XS];
    __shared__ float ws[2][192 * WS];
    __shared__ float ts[64 * 65];        // epilogue staging
    const int t = threadIdx.x, warp = t >> 5, lane = t & 31;
    const int lr4 = lane >> 2, cq = lane & 3;
    const int m0 = blockIdx.x * 64, rl = warp * 16 + lr4;
    const uint32_t xs_b = (uint32_t)__cvta_generic_to_shared(&xs[0][0]);
    const uint32_t ws_b = (uint32_t)__cvta_generic_to_shared(&ws[0][0]);

    float acc[3][8][4];
#pragma unroll
    for (int m = 0; m < 3; m++)
#pragma unroll
        for (int n = 0; n < 8; n++)
            acc[m][n][0] = acc[m][n][1] = acc[m][n][2] = acc[m][n][3] = 0.f;

    auto issue = [&](int kc, int st) {
#pragma unroll
        for (int i = 0; i < 2; i++) {
            int c = i * 128 + t, r = c >> 2, ch = c & 3;
            cp16(xs_b + (uint32_t)(st * 64 * XS + r * XS + ch * 4) * 4,
                 x + (size_t)(m0 + r) * EMB_DIM + kc * 16 + ch * 4);
        }
#pragma unroll
        for (int i = 0; i < 6; i++) {
            int c = i * 128 + t, row = c >> 2, ch = c & 3;
            cp16(ws_b + (uint32_t)(st * 192 * WS + row * WS + ch * 4) * 4,
                 g_Wt + (size_t)row * 1024 + kc * 16 + ch * 4);
        }
        CP_COMMIT();
    };

    issue(0, 0);
    for (int kc = 0; kc < 64; kc++) {
        const int st = kc & 1;
        if (kc < 63) { issue(kc + 1, st ^ 1); CP_WAIT1(); } else { CP_WAIT0(); }
        __syncthreads();

        uint32_t a[2][4];
#pragma unroll
        for (int kk = 0; kk < 2; kk++) {
            a[kk][0] = fu(f2tf(xs[st][rl * XS + kk * 8 + cq]));
            a[kk][1] = fu(f2tf(xs[st][(rl + 8) * XS + kk * 8 + cq]));
            a[kk][2] = fu(f2tf(xs[st][rl * XS + kk * 8 + cq + 4]));
            a[kk][3] = fu(f2tf(xs[st][(rl + 8) * XS + kk * 8 + cq + 4]));
        }
#pragma unroll
        for (int m = 0; m < 3; m++)
#pragma unroll
            for (int n = 0; n < 8; n++)
#pragma unroll
                for (int kk = 0; kk < 2; kk++) {
                    float2 b = *reinterpret_cast<float2*>(
                        &ws[st][(m * 64 + n * 8 + lr4) * WS + kk * 8 + 2 * cq]);
                    mma8(acc[m][n], a[kk], fu(b.x), fu(b.y));
                }
        __syncthreads();
    }

    const int bb = m0 >> 12;
    const int sbase = m0 & 4095;
    const float scl[2] = {0.125f, 1.0f};

    // Q then K: stage ts[row][col_perm], store coalesced rows
#pragma unroll 1
    for (int mat = 0; mat < 2; mat++) {
        float* dst = mat ? g_K : g_Q;
#pragma unroll
        for (int n = 0; n < 8; n++) {
            int p0 = n * 8 + perm8(2 * cq), p1 = n * 8 + perm8(2 * cq + 1);
            ts[rl * 65 + p0]       = f2tf(acc[mat][n][0] * scl[mat]);
            ts[rl * 65 + p1]       = f2tf(acc[mat][n][1] * scl[mat]);
            ts[(rl + 8) * 65 + p0] = f2tf(acc[mat][n][2] * scl[mat]);
            ts[(rl + 8) * 65 + p1] = f2tf(acc[mat][n][3] * scl[mat]);
        }
        __syncthreads();
        {
            int row = t >> 1, off = (t & 1) * 32;
            float* o = dst + (size_t)(m0 + row) * 64 + off;
#pragma unroll
            for (int i = 0; i < 8; i++) {
                float4 v = make_float4(ts[row*65+off+4*i], ts[row*65+off+4*i+1],
                                       ts[row*65+off+4*i+2], ts[row*65+off+4*i+3]);
                *reinterpret_cast<float4*>(o + 4 * i) = v;
            }
        }
        __syncthreads();
    }
    // V: stage ts[dim][s_perm_local], store coalesced along s
    {
        const int spl0 = (rl & ~7) | perm8(rl & 7);
        const int spl1 = spl0 + 8;
#pragma unroll
        for (int n = 0; n < 8; n++) {
            int c0 = n * 8 + 2 * cq, c1 = c0 + 1;
            ts[c0 * 65 + spl0] = f2tf(acc[2][n][0]);
            ts[c1 * 65 + spl0] = f2tf(acc[2][n][1]);
            ts[c0 * 65 + spl1] = f2tf(acc[2][n][2]);
            ts[c1 * 65 + spl1] = f2tf(acc[2][n][3]);
        }
        __syncthreads();
        int d = t >> 1, off = (t & 1) * 32;
        float* o = g_VT + ((size_t)bb * 64 + d) * SEQ + sbase + off;
#pragma unroll
        for (int i = 0; i < 8; i++) {
            float4 v = make_float4(ts[d*65+off+4*i], ts[d*65+off+4*i+1],
                                   ts[d*65+off+4*i+2], ts[d*65+off+4*i+3]);
            *reinterpret_cast<float4*>(o + 4 * i) = v;
        }
    }
}

// ---------------------------------------------------------------------------
// Kernel 2: split-KV causal flash attention. 640 near-uniform tasks (chunks
// of <=16 key-tiles); partials (o, m, l) to scratch; combine kernel merges.
// ---------------------------------------------------------------------------
#define KVS 72
#define ATTN_SMEM (2 * 2 * 64 * KVS * 4)   // 73728 B
__global__ __launch_bounds__(128, 3) void attn_kernel()
{
    extern __shared__ float sm[];
    const int t = threadIdx.x, warp = t >> 5, lane = t & 31;
    const int lr4 = lane >> 2, cq = lane & 3;
    const int rl = warp * 16 + lr4;
    const uint32_t sm_b = (uint32_t)__cvta_generic_to_shared(sm);

    // task decode (reversed so big tasks launch first)
    const int tk = 639 - (int)blockIdx.x;
    const int b = tk / 160, r = tk % 160;
    int qi, ch, nc;
    if (r < 16)      { qi = r;                ch = 0;            nc = 1; }
    else if (r < 48) { qi = 16 + (r-16)/2;    ch = (r-16)%2;     nc = 2; }
    else if (r < 96) { qi = 32 + (r-48)/3;    ch = (r-48)%3;     nc = 3; }
    else             { qi = 48 + (r-96)/4;    ch = (r-96)%4;     nc = 4; }
    const int T = qi + 1;
    const int js = (ch * T) / nc, je = ((ch + 1) * T) / nc;
    const int q0 = qi * 64;

    // Q fragments from gmem (tf32, scaled, pair-permuted)
    uint32_t aq[8][4];
    {
        const float* Qr0 = g_Q + (size_t)(b * SEQ + q0 + rl) * 64;
        const float* Qr1 = Qr0 + 8 * 64;
#pragma unroll
        for (int kk = 0; kk < 8; kk++) {
            float2 v0 = *reinterpret_cast<const float2*>(Qr0 + kk * 8 + 2 * cq);
            float2 v1 = *reinterpret_cast<const float2*>(Qr1 + kk * 8 + 2 * cq);
            aq[kk][0] = fu(v0.x); aq[kk][2] = fu(v0.y);
            aq[kk][1] = fu(v1.x); aq[kk][3] = fu(v1.y);
        }
    }

    auto issue = [&](int j, int st) {
        const float* Kg = g_K + ((size_t)b * SEQ + j * 64) * 64;
        const float* Vg = g_VT + (size_t)b * 64 * SEQ + j * 64;
        const uint32_t kb = sm_b + (uint32_t)st * 2 * 64 * KVS * 4;
        const uint32_t vb = kb + 64 * KVS * 4;
#pragma unroll
        for (int i = 0; i < 8; i++) {
            int c = i * 128 + t, rr = c >> 4, chh = c & 15;
            cp16(kb + (uint32_t)(rr * KVS + chh * 4) * 4, Kg + rr * 64 + chh * 4);
        }
#pragma unroll
        for (int i = 0; i < 8; i++) {
            int c = i * 128 + t, rr = c >> 4, chh = c & 15;
            cp16(vb + (uint32_t)(rr * KVS + chh * 4) * 4, Vg + (size_t)rr * SEQ + chh * 4);
        }
        CP_COMMIT();
    };

    float m0 = -1e30f, m1 = -1e30f, l0 = 0.f, l1 = 0.f;
    float o[8][4];
#pragma unroll
    for (int n = 0; n < 8; n++) { o[n][0] = o[n][1] = o[n][2] = o[n][3] = 0.f; }

    issue(js, 0);
    for (int j = js; j < je; j++) {
        const int st = (j - js) & 1;
        if (j < je - 1) { issue(j + 1, st ^ 1); CP_WAIT1(); } else { CP_WAIT0(); }
        __syncthreads();
        const float* ks = sm + st * 2 * 64 * KVS;
        const float* vs = ks + 64 * KVS;

        float s[8][4];
#pragma unroll
        for (int n = 0; n < 8; n++) { s[n][0] = s[n][1] = s[n][2] = s[n][3] = 0.f; }
#pragma unroll
        for (int n = 0; n < 8; n++)
#pragma unroll
            for (int kk = 0; kk < 8; kk++) {
                float2 bb = *reinterpret_cast<const float2*>(
                    &ks[(n * 8 + lr4) * KVS + kk * 8 + 2 * cq]);
                mma8(s[n], aq[kk], fu(bb.x), fu(bb.y));
            }

        if (j == qi) {
#pragma unroll
            for (int n = 0; n < 8; n++) {
                int c0 = n * 8 + 2 * cq;
                if (c0     > rl)     s[n][0] = -1e30f;
                if (c0 + 1 > rl)     s[n][1] = -1e30f;
                if (c0     > rl + 8) s[n][2] = -1e30f;
                if (c0 + 1 > rl + 8) s[n][3] = -1e30f;
            }
        }

        float nm0 = m0, nm1 = m1;
#pragma unroll
        for (int n = 0; n < 8; n++) {
            nm0 = fmaxf(nm0, fmaxf(s[n][0], s[n][1]));
            nm1 = fmaxf(nm1, fmaxf(s[n][2], s[n][3]));
        }
        nm0 = fmaxf(nm0, __shfl_xor_sync(0xffffffffu, nm0, 1));
        nm0 = fmaxf(nm0, __shfl_xor_sync(0xffffffffu, nm0, 2));
        nm1 = fmaxf(nm1, __shfl_xor_sync(0xffffffffu, nm1, 1));
        nm1 = fmaxf(nm1, __shfl_xor_sync(0xffffffffu, nm1, 2));
        float sc0 = __expf(m0 - nm0), sc1 = __expf(m1 - nm1);
        m0 = nm0; m1 = nm1;

        float sum0 = 0.f, sum1 = 0.f;
#pragma unroll
        for (int n = 0; n < 8; n++) {
            float p0 = __expf(s[n][0] - nm0);
            float p1 = __expf(s[n][1] - nm0);
            float p2 = __expf(s[n][2] - nm1);
            float p3 = __expf(s[n][3] - nm1);
            sum0 += p0 + p1; sum1 += p2 + p3;
            s[n][0] = f2tf(p0); s[n][1] = f2tf(p1);
            s[n][2] = f2tf(p2); s[n][3] = f2tf(p3);
        }
        sum0 += __shfl_xor_sync(0xffffffffu, sum0, 1);
        sum0 += __shfl_xor_sync(0xffffffffu, sum0, 2);
        sum1 += __shfl_xor_sync(0xffffffffu, sum1, 1);
        sum1 += __shfl_xor_sync(0xffffffffu, sum1, 2);
        l0 = l0 * sc0 + sum0;
        l1 = l1 * sc1 + sum1;
#pragma unroll
        for (int n = 0; n < 8; n++) {
            o[n][0] *= sc0; o[n][1] *= sc0; o[n][2] *= sc1; o[n][3] *= sc1;
        }

        const int src0 = (lane & 28) | (cq >> 1);
        const int src1 = src0 + 2;
        const bool odd = (cq & 1);
#pragma unroll
        for (int tt = 0; tt < 8; tt++) {
            float v00 = __shfl_sync(0xffffffffu, s[tt][0], src0);
            float v01 = __shfl_sync(0xffffffffu, s[tt][1], src0);
            float w00 = __shfl_sync(0xffffffffu, s[tt][2], src0);
            float w01 = __shfl_sync(0xffffffffu, s[tt][3], src0);
            float v10 = __shfl_sync(0xffffffffu, s[tt][0], src1);
            float v11 = __shfl_sync(0xffffffffu, s[tt][1], src1);
            float w10 = __shfl_sync(0xffffffffu, s[tt][2], src1);
            float w11 = __shfl_sync(0xffffffffu, s[tt][3], src1);
            uint32_t a[4];
            a[0] = fu(odd ? v01 : v00);
            a[1] = fu(odd ? w01 : w00);
            a[2] = fu(odd ? v11 : v10);
            a[3] = fu(odd ? w11 : w10);
#pragma unroll
            for (int n = 0; n < 8; n++) {
                float2 bb = *reinterpret_cast<const float2*>(
                    &vs[(n * 8 + lr4) * KVS + tt * 8 + 2 * cq]);
                mma8(o[n], a, fu(bb.x), fu(bb.y));
            }
        }
        __syncthreads();
    }

    // write partials (unnormalized o, plus m and l)
    const int slot = (b * 64 + qi) * 4 + ch;
    float* po = g_po + (size_t)slot * 4096;
#pragma unroll
    for (int n = 0; n < 8; n++) {
        int c = n * 8 + 2 * cq;
        *reinterpret_cast<float2*>(po + rl * 64 + c)       = make_float2(o[n][0], o[n][1]);
        *reinterpret_cast<float2*>(po + (rl + 8) * 64 + c) = make_float2(o[n][2], o[n][3]);
    }
    if (cq == 0) {
        g_pm[slot * 64 + rl]     = m0;  g_pl[slot * 64 + rl]     = l0;
        g_pm[slot * 64 + rl + 8] = m1;  g_pl[slot * 64 + rl + 8] = l1;
    }
}

// ---------------------------------------------------------------------------
// Kernel 3: combine partials -> final output. Bandwidth-bound.
// ---------------------------------------------------------------------------
__global__ __launch_bounds__(256) void combine_kernel(float* __restrict__ out)
{
    const int idx = blockIdx.x * 256 + threadIdx.x;   // 262144 threads
    const int row = idx >> 4, c4 = (idx & 15) * 4;
    const int b = row >> 12, s = row & 4095;
    const int qt = s >> 6, r64 = s & 63;
    const int nc = (qt >> 4) + 1;
    const int base = (b * 64 + qt) * 4;

    float mv[4];
    float M = -1e30f;
#pragma unroll 4
    for (int c = 0; c < nc; c++) {
        mv[c] = g_pm[(base + c) * 64 + r64];
        M = fmaxf(M, mv[c]);
    }
    float4 acc = make_float4(0.f, 0.f, 0.f, 0.f);
    float l = 0.f;
#pragma unroll 4
    for (int c = 0; c < nc; c++) {
        float w = __expf(mv[c] - M);
        const float4 o = *reinterpret_cast<const float4*>(
            g_po + (size_t)(base + c) * 4096 + r64 * 64 + c4);
        acc.x += w * o.x; acc.y += w * o.y; acc.z += w * o.z; acc.w += w * o.w;
        l += w * g_pl[(base + c) * 64 + r64];
    }
    const float inv = 1.f / l;
    acc.x *= inv; acc.y *= inv; acc.z *= inv; acc.w *= inv;
    *reinterpret_cast<float4*>(out + (size_t)row * 64 + c4) = acc;
}

extern "C" void kernel_launch(void* const* d_in, const int* in_sizes, int n_in,
                              void* d_out, int out_size) {
    const float* x  = (const float*)d_in[0];
    const float* Wq = (const float*)d_in[1];
    const float* Wk = (const float*)d_in[2];
    const float* Wv = (const float*)d_in[3];
    float* out = (float*)d_out;

    w_prep_kernel<<<dim3(16, 3), 256>>>(Wq, Wk, Wv);
    qkv_proj_kernel<<<MTOT / 64, 128>>>(x);
    cudaFuncSetAttribute(attn_kernel, cudaFuncAttributeMaxDynamicSharedMemorySize, ATTN_SMEM);
    attn_kernel<<<640, 128, ATTN_SMEM>>>();
    combine_kernel<<<1024, 256>>>(out);
}

// round 5
// speedup vs baseline: 1.9681x; 1.6692x over previous
#include <cuda_runtime.h>
#include <cstdint>

#define HEAD_DIM 64
#define EMB_DIM 1024
#define BATCH 4
#define SEQ 4096
#define MTOT (BATCH*SEQ)

// Pre-rounded tf32 scratch. Q,K: [m][64] head-dim pairs (c, c+4) interleaved
// per 8-group (perm8). V: transposed [b][dim][s], key order NATURAL.
__device__ float g_Q[(size_t)MTOT * 64];
__device__ float g_K[(size_t)MTOT * 64];
__device__ float g_VT[(size_t)BATCH * 64 * SEQ];
__device__ float g_Wt[3 * 64 * 1024];   // [mat][n][k] transposed, k pair-permuted, tf32

// split-KV partial scratch: slot = ((b*64 + qtile)*4 + chunk)
__device__ float g_po[(size_t)4 * 64 * 4 * 64 * 64];  // [slot][row64][col64]
__device__ float g_pm[4 * 64 * 4 * 64];
__device__ float g_pl[4 * 64 * 4 * 64];

__device__ __forceinline__ float f2tf(float f) {
    uint32_t r; asm("cvt.rna.tf32.f32 %0, %1;" : "=r"(r) : "f"(f));
    return __uint_as_float(r);
}
__device__ __forceinline__ uint32_t fu(float f) { return __float_as_uint(f); }

__device__ __forceinline__ void mma8(float* c, const uint32_t* a, uint32_t b0, uint32_t b1) {
    asm volatile(
        "mma.sync.aligned.m16n8k8.row.col.f32.tf32.tf32.f32 "
        "{%0,%1,%2,%3}, {%4,%5,%6,%7}, {%8,%9}, {%0,%1,%2,%3};"
        : "+f"(c[0]), "+f"(c[1]), "+f"(c[2]), "+f"(c[3])
        : "r"(a[0]), "r"(a[1]), "r"(a[2]), "r"(a[3]), "r"(b0), "r"(b1));
}

__device__ __forceinline__ void cp16(uint32_t dst, const void* src) {
    asm volatile("cp.async.cg.shared.global [%0], [%1], 16;" :: "r"(dst), "l"(src));
}
#define CP_COMMIT() asm volatile("cp.async.commit_group;")
#define CP_WAIT0()  asm volatile("cp.async.wait_group 0;")

// head-dim pair-permutation: logical j -> phys 2*(j&3) + (j>>2)
// (phys 2c holds logical c; phys 2c+1 holds logical c+4 -> LDS.64 B/A frags)
__device__ __forceinline__ int perm8(int j) { return 2 * (j & 3) + (j >> 2); }

// ---------------------------------------------------------------------------
// Kernel 0: round W to tf32, transpose to [n][k], permute k pairs.
// ---------------------------------------------------------------------------
__global__ void w_prep_kernel(const float* __restrict__ Wq,
                              const float* __restrict__ Wk,
                              const float* __restrict__ Wv) {
    __shared__ float ts[64][65];
    const float* W = (blockIdx.y == 0) ? Wq : (blockIdx.y == 1) ? Wk : Wv;
    const int kt = blockIdx.x;
    const int t = threadIdx.x;   // 256 threads
    {
        int r = t >> 2, c4 = (t & 3) * 16;
        const float* src = W + (size_t)(kt * 64 + r) * 64 + c4;
        const float4 v0 = *reinterpret_cast<const float4*>(src);
        const float4 v1 = *reinterpret_cast<const float4*>(src + 4);
        const float4 v2 = *reinterpret_cast<const float4*>(src + 8);
        const float4 v3 = *reinterpret_cast<const float4*>(src + 12);
        ts[r][c4+0]=f2tf(v0.x); ts[r][c4+1]=f2tf(v0.y); ts[r][c4+2]=f2tf(v0.z); ts[r][c4+3]=f2tf(v0.w);
        ts[r][c4+4]=f2tf(v1.x); ts[r][c4+5]=f2tf(v1.y); ts[r][c4+6]=f2tf(v1.z); ts[r][c4+7]=f2tf(v1.w);
        ts[r][c4+8]=f2tf(v2.x); ts[r][c4+9]=f2tf(v2.y); ts[r][c4+10]=f2tf(v2.z); ts[r][c4+11]=f2tf(v2.w);
        ts[r][c4+12]=f2tf(v3.x); ts[r][c4+13]=f2tf(v3.y); ts[r][c4+14]=f2tf(v3.z); ts[r][c4+15]=f2tf(v3.w);
    }
    __syncthreads();
    float* out = g_Wt + (size_t)blockIdx.y * 64 * 1024;
#pragma unroll
    for (int i = 0; i < 16; i++) {
        int idx = i * 256 + t, n = idx >> 6, r = idx & 63;
        int rp = (r & ~7) | perm8(r & 7);
        out[(size_t)n * 1024 + kt * 64 + rp] = ts[r][n];
    }
}

// ---------------------------------------------------------------------------
// Kernel 1: fused QKV projection, 384 threads: warps 0-3 -> Q, 4-7 -> K,
// 8-11 -> V (32 accum regs/thread). x tile shared by all three groups.
// ---------------------------------------------------------------------------
#define XS 20
#define WS 24
__global__ __launch_bounds__(384, 2) void qkv_proj_kernel(const float* __restrict__ x)
{
    __shared__ float xs[2][64 * XS];      // raw fp32 x tiles
    __shared__ float ws[2][192 * WS];     // tf32 W^T tiles (3 mats x 64 rows x 16 k)
    __shared__ float ts[64 * 65];         // epilogue staging
    const int t = threadIdx.x, warp = t >> 5, lane = t & 31;
    const int grp = warp >> 2, wg = warp & 3;
    const int lr4 = lane >> 2, cq = lane & 3;
    const int m0 = blockIdx.x * 64, rl = wg * 16 + lr4;
    const uint32_t xs_b = (uint32_t)__cvta_generic_to_shared(&xs[0][0]);
    const uint32_t ws_b = (uint32_t)__cvta_generic_to_shared(&ws[0][0]);

    float acc[8][4];
#pragma unroll
    for (int n = 0; n < 8; n++) acc[n][0] = acc[n][1] = acc[n][2] = acc[n][3] = 0.f;

    auto issue = [&](int kc, int st) {
        if (t < 256) {   // x tile: 64 rows x 64B
            int r = t >> 2, ch = t & 3;
            cp16(xs_b + (uint32_t)(st * 64 * XS + r * XS + ch * 4) * 4,
                 x + (size_t)(m0 + r) * EMB_DIM + kc * 16 + ch * 4);
        }
#pragma unroll
        for (int i = 0; i < 2; i++) {   // W tiles: 192 rows x 64B
            int c = i * 384 + t, row = c >> 2, ch = c & 3;
            cp16(ws_b + (uint32_t)(st * 192 * WS + row * WS + ch * 4) * 4,
                 g_Wt + (size_t)row * 1024 + kc * 16 + ch * 4);
        }
        CP_COMMIT();
    };

    issue(0, 0);
    for (int kc = 0; kc < 64; kc++) {
        const int st = kc & 1;
        CP_WAIT0();
        __syncthreads();
        if (kc < 63) issue(kc + 1, st ^ 1);

        uint32_t a[2][4];
#pragma unroll
        for (int kk = 0; kk < 2; kk++) {
            a[kk][0] = fu(f2tf(xs[st][rl * XS + kk * 8 + cq]));
            a[kk][1] = fu(f2tf(xs[st][(rl + 8) * XS + kk * 8 + cq]));
            a[kk][2] = fu(f2tf(xs[st][rl * XS + kk * 8 + cq + 4]));
            a[kk][3] = fu(f2tf(xs[st][(rl + 8) * XS + kk * 8 + cq + 4]));
        }
#pragma unroll
        for (int n = 0; n < 8; n++)
#pragma unroll
            for (int kk = 0; kk < 2; kk++) {
                float2 b = *reinterpret_cast<float2*>(
                    &ws[st][(grp * 64 + n * 8 + lr4) * WS + kk * 8 + 2 * cq]);
                mma8(acc[n], a[kk], fu(b.x), fu(b.y));
            }
    }

    const int bb = m0 >> 12;
    const int sbase = m0 & 4095;

    // Epilogue: three sequential staged passes through ts, coalesced stores.
#pragma unroll 1
    for (int mat = 0; mat < 3; mat++) {
        __syncthreads();
        if (grp == mat) {
            if (mat < 2) {   // Q (scaled) / K: rows, head-dim cols perm8
                const float scl = (mat == 0) ? 0.125f : 1.0f;
#pragma unroll
                for (int n = 0; n < 8; n++) {
                    int p0 = n * 8 + perm8(2 * cq), p1 = n * 8 + perm8(2 * cq + 1);
                    ts[rl * 65 + p0]       = f2tf(acc[n][0] * scl);
                    ts[rl * 65 + p1]       = f2tf(acc[n][1] * scl);
                    ts[(rl + 8) * 65 + p0] = f2tf(acc[n][2] * scl);
                    ts[(rl + 8) * 65 + p1] = f2tf(acc[n][3] * scl);
                }
            } else {         // V: transposed [dim][s_local], key order natural
#pragma unroll
                for (int n = 0; n < 8; n++) {
                    int c0 = n * 8 + 2 * cq, c1 = c0 + 1;
                    ts[c0 * 65 + rl]     = f2tf(acc[n][0]);
                    ts[c1 * 65 + rl]     = f2tf(acc[n][1]);
                    ts[c0 * 65 + rl + 8] = f2tf(acc[n][2]);
                    ts[c1 * 65 + rl + 8] = f2tf(acc[n][3]);
                }
            }
        }
        __syncthreads();
        if (t < 256) {
            int row = t >> 2, off = (t & 3) * 16;
            float* o;
            if (mat == 0)      o = g_Q + (size_t)(m0 + row) * 64 + off;
            else if (mat == 1) o = g_K + (size_t)(m0 + row) * 64 + off;
            else               o = g_VT + ((size_t)bb * 64 + row) * SEQ + sbase + off;
#pragma unroll
            for (int i = 0; i < 4; i++) {
                float4 v = make_float4(ts[row*65+off+4*i], ts[row*65+off+4*i+1],
                                       ts[row*65+off+4*i+2], ts[row*65+off+4*i+3]);
                *reinterpret_cast<float4*>(o + 4 * i) = v;
            }
        }
    }
}

// ---------------------------------------------------------------------------
// Kernel 2: split-KV causal flash attention. Shuffle-free P->A conversion
// (a = {c0, c2, c1, c3}; V keys natural). Single syncthreads per iteration.
// ---------------------------------------------------------------------------
#define KVS 72
#define ATTN_SMEM (2 * 2 * 64 * KVS * 4)   // 73728 B
__global__ __launch_bounds__(128, 3) void attn_kernel()
{
    extern __shared__ float sm[];
    const int t = threadIdx.x, warp = t >> 5, lane = t & 31;
    const int lr4 = lane >> 2, cq = lane & 3;
    const int rl = warp * 16 + lr4;
    const uint32_t sm_b = (uint32_t)__cvta_generic_to_shared(sm);

    // task decode (reversed so big tasks launch first)
    const int tk = 639 - (int)blockIdx.x;
    const int b = tk / 160, r = tk % 160;
    int qi, ch, nc;
    if (r < 16)      { qi = r;                ch = 0;            nc = 1; }
    else if (r < 48) { qi = 16 + (r-16)/2;    ch = (r-16)%2;     nc = 2; }
    else if (r < 96) { qi = 32 + (r-48)/3;    ch = (r-48)%3;     nc = 3; }
    else             { qi = 48 + (r-96)/4;    ch = (r-96)%4;     nc = 4; }
    const int T = qi + 1;
    const int js = (ch * T) / nc, je = ((ch + 1) * T) / nc;
    const int q0 = qi * 64;

    // Q fragments from gmem (tf32, scaled, pair-permuted)
    uint32_t aq[8][4];
    {
        const float* Qr0 = g_Q + (size_t)(b * SEQ + q0 + rl) * 64;
        const float* Qr1 = Qr0 + 8 * 64;
#pragma unroll
        for (int kk = 0; kk < 8; kk++) {
            float2 v0 = *reinterpret_cast<const float2*>(Qr0 + kk * 8 + 2 * cq);
            float2 v1 = *reinterpret_cast<const float2*>(Qr1 + kk * 8 + 2 * cq);
            aq[kk][0] = fu(v0.x); aq[kk][2] = fu(v0.y);
            aq[kk][1] = fu(v1.x); aq[kk][3] = fu(v1.y);
        }
    }

    auto issue = [&](int j, int st) {
        const float* Kg = g_K + ((size_t)b * SEQ + j * 64) * 64;
        const float* Vg = g_VT + (size_t)b * 64 * SEQ + j * 64;
        const uint32_t kb = sm_b + (uint32_t)st * 2 * 64 * KVS * 4;
        const uint32_t vb = kb + 64 * KVS * 4;
#pragma unroll
        for (int i = 0; i < 8; i++) {
            int c = i * 128 + t, rr = c >> 4, chh = c & 15;
            cp16(kb + (uint32_t)(rr * KVS + chh * 4) * 4, Kg + rr * 64 + chh * 4);
        }
#pragma unroll
        for (int i = 0; i < 8; i++) {
            int c = i * 128 + t, rr = c >> 4, chh = c & 15;
            cp16(vb + (uint32_t)(rr * KVS + chh * 4) * 4, Vg + (size_t)rr * SEQ + chh * 4);
        }
        CP_COMMIT();
    };

    float m0 = -1e30f, m1 = -1e30f, l0 = 0.f, l1 = 0.f;
    float o[8][4];
#pragma unroll
    for (int n = 0; n < 8; n++) { o[n][0] = o[n][1] = o[n][2] = o[n][3] = 0.f; }

    issue(js, 0);
    for (int j = js; j < je; j++) {
        const int st = (j - js) & 1;
        CP_WAIT0();
        __syncthreads();
        if (j < je - 1) issue(j + 1, st ^ 1);
        const float* ks = sm + st * 2 * 64 * KVS;
        const float* vs = ks + 64 * KVS;

        // S = Q @ K^T
        float s[8][4];
#pragma unroll
        for (int n = 0; n < 8; n++) { s[n][0] = s[n][1] = s[n][2] = s[n][3] = 0.f; }
#pragma unroll
        for (int n = 0; n < 8; n++)
#pragma unroll
            for (int kk = 0; kk < 8; kk++) {
                float2 bb = *reinterpret_cast<const float2*>(
                    &ks[(n * 8 + lr4) * KVS + kk * 8 + 2 * cq]);
                mma8(s[n], aq[kk], fu(bb.x), fu(bb.y));
            }

        if (j == qi) {   // causal mask on diagonal tile
#pragma unroll
            for (int n = 0; n < 8; n++) {
                int c0 = n * 8 + 2 * cq;
                if (c0     > rl)     s[n][0] = -1e30f;
                if (c0 + 1 > rl)     s[n][1] = -1e30f;
                if (c0     > rl + 8) s[n][2] = -1e30f;
                if (c0 + 1 > rl + 8) s[n][3] = -1e30f;
            }
        }

        // online softmax (rows rl, rl+8)
        float nm0 = m0, nm1 = m1;
#pragma unroll
        for (int n = 0; n < 8; n++) {
            nm0 = fmaxf(nm0, fmaxf(s[n][0], s[n][1]));
            nm1 = fmaxf(nm1, fmaxf(s[n][2], s[n][3]));
        }
        nm0 = fmaxf(nm0, __shfl_xor_sync(0xffffffffu, nm0, 1));
        nm0 = fmaxf(nm0, __shfl_xor_sync(0xffffffffu, nm0, 2));
        nm1 = fmaxf(nm1, __shfl_xor_sync(0xffffffffu, nm1, 1));
        nm1 = fmaxf(nm1, __shfl_xor_sync(0xffffffffu, nm1, 2));
        float sc0 = __expf(m0 - nm0), sc1 = __expf(m1 - nm1);
        m0 = nm0; m1 = nm1;

        float sum0 = 0.f, sum1 = 0.f;
#pragma unroll
        for (int n = 0; n < 8; n++) {
            float p0 = __expf(s[n][0] - nm0);
            float p1 = __expf(s[n][1] - nm0);
            float p2 = __expf(s[n][2] - nm1);
            float p3 = __expf(s[n][3] - nm1);
            sum0 += p0 + p1; sum1 += p2 + p3;
            s[n][0] = f2tf(p0); s[n][1] = f2tf(p1);
            s[n][2] = f2tf(p2); s[n][3] = f2tf(p3);
        }
        sum0 += __shfl_xor_sync(0xffffffffu, sum0, 1);
        sum0 += __shfl_xor_sync(0xffffffffu, sum0, 2);
        sum1 += __shfl_xor_sync(0xffffffffu, sum1, 1);
        sum1 += __shfl_xor_sync(0xffffffffu, sum1, 2);
        l0 = l0 * sc0 + sum0;
        l1 = l1 * sc1 + sum1;
#pragma unroll
        for (int n = 0; n < 8; n++) {
            o[n][0] *= sc0; o[n][1] *= sc0; o[n][2] *= sc1; o[n][3] *= sc1;
        }

        // O += P @ V — shuffle-free: C layout {c0,c1;c2,c3} -> A = {c0,c2,c1,c3}
        // (A k-slot cq <- logical key 2cq = c0; slot cq+4 <- key 2cq+1 = c1;
        //  V rows natural, so B float2 at 2cq supplies exactly those keys.)
#pragma unroll
        for (int tt = 0; tt < 8; tt++) {
            uint32_t a[4];
            a[0] = fu(s[tt][0]);
            a[1] = fu(s[tt][2]);
            a[2] = fu(s[tt][1]);
            a[3] = fu(s[tt][3]);
#pragma unroll
            for (int n = 0; n < 8; n++) {
                float2 bb = *reinterpret_cast<const float2*>(
                    &vs[(n * 8 + lr4) * KVS + tt * 8 + 2 * cq]);
                mma8(o[n], a, fu(bb.x), fu(bb.y));
            }
        }
    }

    // write partials (unnormalized o, plus m and l)
    const int slot = (b * 64 + qi) * 4 + ch;
    float* po = g_po + (size_t)slot * 4096;
#pragma unroll
    for (int n = 0; n < 8; n++) {
        int c = n * 8 + 2 * cq;
        *reinterpret_cast<float2*>(po + rl * 64 + c)       = make_float2(o[n][0], o[n][1]);
        *reinterpret_cast<float2*>(po + (rl + 8) * 64 + c) = make_float2(o[n][2], o[n][3]);
    }
    if (cq == 0) {
        g_pm[slot * 64 + rl]     = m0;  g_pl[slot * 64 + rl]     = l0;
        g_pm[slot * 64 + rl + 8] = m1;  g_pl[slot * 64 + rl + 8] = l1;
    }
}

// ---------------------------------------------------------------------------
// Kernel 3: combine partials -> final output. Bandwidth-bound.
// ---------------------------------------------------------------------------
__global__ __launch_bounds__(256) void combine_kernel(float* __restrict__ out)
{
    const int idx = blockIdx.x * 256 + threadIdx.x;
    const int row = idx >> 4, c4 = (idx & 15) * 4;
    const int b = row >> 12, s = row & 4095;
    const int qt = s >> 6, r64 = s & 63;
    const int nc = (qt >> 4) + 1;
    const int base = (b * 64 + qt) * 4;

    float mv[4];
    float M = -1e30f;
#pragma unroll 4
    for (int c = 0; c < nc; c++) {
        mv[c] = g_pm[(base + c) * 64 + r64];
        M = fmaxf(M, mv[c]);
    }
    float4 acc = make_float4(0.f, 0.f, 0.f, 0.f);
    float l = 0.f;
#pragma unroll 4
    for (int c = 0; c < nc; c++) {
        float w = __expf(mv[c] - M);
        const float4 o = *reinterpret_cast<const float4*>(
            g_po + (size_t)(base + c) * 4096 + r64 * 64 + c4);
        acc.x += w * o.x; acc.y += w * o.y; acc.z += w * o.z; acc.w += w * o.w;
        l += w * g_pl[(base + c) * 64 + r64];
    }
    const float inv = 1.f / l;
    acc.x *= inv; acc.y *= inv; acc.z *= inv; acc.w *= inv;
    *reinterpret_cast<float4*>(out + (size_t)row * 64 + c4) = acc;
}

extern "C" void kernel_launch(void* const* d_in, const int* in_sizes, int n_in,
                              void* d_out, int out_size) {
    const float* x  = (const float*)d_in[0];
    const float* Wq = (const float*)d_in[1];
    const float* Wk = (const float*)d_in[2];
    const float* Wv = (const float*)d_in[3];
    float* out = (float*)d_out;

    w_prep_kernel<<<dim3(16, 3), 256>>>(Wq, Wk, Wv);
    qkv_proj_kernel<<<MTOT / 64, 384>>>(x);
    cudaFuncSetAttribute(attn_kernel, cudaFuncAttributeMaxDynamicSharedMemorySize, ATTN_SMEM);
    attn_kernel<<<640, 128, ATTN_SMEM>>>();
    combine_kernel<<<1024, 256>>>(out);
}

// round 7
// speedup vs baseline: 2.0451x; 1.0391x over previous
#include <cuda_runtime.h>
#include <cstdint>

#define HEAD_DIM 64
#define EMB_DIM 1024
#define BATCH 4
#define SEQ 4096
#define MTOT (BATCH*SEQ)

// Q pre-scale: (1/sqrt(64)) * log2(e)  -> softmax computed base-2
#define QSCALE 0.18033688011112042f

// Pre-rounded tf32 scratch. Q,K: [m][64] head-dim pairs (c, c+4) interleaved
// per 8-group (perm8). V: transposed [b][dim][s], key order NATURAL.
__device__ float g_Q[(size_t)MTOT * 64];
__device__ float g_K[(size_t)MTOT * 64];
__device__ float g_VT[(size_t)BATCH * 64 * SEQ];
__device__ float g_Wt[3 * 64 * 1024];   // [n][k] W^T rows Q|K|V, k pair-permuted, tf32

// split-KV partial scratch: slot = ((b*32 + qtile128)*8 + chunk)
__device__ float g_po[(size_t)1024 * 128 * 64];   // [slot][row128][col64]
__device__ float g_pm[1024 * 128];
__device__ float g_pl[1024 * 128];

__device__ __forceinline__ float f2tf(float f) {
    uint32_t r; asm("cvt.rna.tf32.f32 %0, %1;" : "=r"(r) : "f"(f));
    return __uint_as_float(r);
}
__device__ __forceinline__ uint32_t fu(float f) { return __float_as_uint(f); }
__device__ __forceinline__ float ex2(float x) {
    float r; asm("ex2.approx.f32 %0, %1;" : "=f"(r) : "f"(x)); return r;
}

__device__ __forceinline__ void mma8(float* c, const uint32_t* a, uint32_t b0, uint32_t b1) {
    asm volatile(
        "mma.sync.aligned.m16n8k8.row.col.f32.tf32.tf32.f32 "
        "{%0,%1,%2,%3}, {%4,%5,%6,%7}, {%8,%9}, {%0,%1,%2,%3};"
        : "+f"(c[0]), "+f"(c[1]), "+f"(c[2]), "+f"(c[3])
        : "r"(a[0]), "r"(a[1]), "r"(a[2]), "r"(a[3]), "r"(b0), "r"(b1));
}

__device__ __forceinline__ void cp16(uint32_t dst, const void* src) {
    asm volatile("cp.async.cg.shared.global [%0], [%1], 16;" :: "r"(dst), "l"(src));
}
#define CP_COMMIT() asm volatile("cp.async.commit_group;")
#define CP_WAIT1()  asm volatile("cp.async.wait_group 1;")
#define CP_WAIT0()  asm volatile("cp.async.wait_group 0;")

__device__ __forceinline__ int perm8(int j) { return 2 * (j & 3) + (j >> 2); }

// ---------------------------------------------------------------------------
// Kernel 0: round W to tf32, transpose to [n][k], permute k pairs.
// ---------------------------------------------------------------------------
__global__ void w_prep_kernel(const float* __restrict__ Wq,
                              const float* __restrict__ Wk,
                              const float* __restrict__ Wv) {
    __shared__ float ts[64][65];
    const float* W = (blockIdx.y == 0) ? Wq : (blockIdx.y == 1) ? Wk : Wv;
    const int kt = blockIdx.x;
    const int t = threadIdx.x;   // 256 threads
    {
        int r = t >> 2, c4 = (t & 3) * 16;
        const float* src = W + (size_t)(kt * 64 + r) * 64 + c4;
        const float4 v0 = *reinterpret_cast<const float4*>(src);
        const float4 v1 = *reinterpret_cast<const float4*>(src + 4);
        const float4 v2 = *reinterpret_cast<const float4*>(src + 8);
        const float4 v3 = *reinterpret_cast<const float4*>(src + 12);
        ts[r][c4+0]=f2tf(v0.x); ts[r][c4+1]=f2tf(v0.y); ts[r][c4+2]=f2tf(v0.z); ts[r][c4+3]=f2tf(v0.w);
        ts[r][c4+4]=f2tf(v1.x); ts[r][c4+5]=f2tf(v1.y); ts[r][c4+6]=f2tf(v1.z); ts[r][c4+7]=f2tf(v1.w);
        ts[r][c4+8]=f2tf(v2.x); ts[r][c4+9]=f2tf(v2.y); ts[r][c4+10]=f2tf(v2.z); ts[r][c4+11]=f2tf(v2.w);
        ts[r][c4+12]=f2tf(v3.x); ts[r][c4+13]=f2tf(v3.y); ts[r][c4+14]=f2tf(v3.z); ts[r][c4+15]=f2tf(v3.w);
    }
    __syncthreads();
    float* out = g_Wt + (size_t)blockIdx.y * 64 * 1024;
#pragma unroll
    for (int i = 0; i < 16; i++) {
        int idx = i * 256 + t, n = idx >> 6, r = idx & 63;
        int rp = (r & ~7) | perm8(r & 7);
        out[(size_t)n * 1024 + kt * 64 + rp] = ts[r][n];
    }
}

// ---------------------------------------------------------------------------
// Kernel 1: fused QKV projection, 384 threads: warps 0-3 -> Q, 4-7 -> K,
// 8-11 -> V. x tile shared by all three groups.
// ---------------------------------------------------------------------------
#define XS 20
#define WS 24
__global__ __launch_bounds__(384, 2) void qkv_proj_kernel(const float* __restrict__ x)
{
    __shared__ float xs[2][64 * XS];
    __shared__ float ws[2][192 * WS];
    __shared__ float ts[64 * 65];
    const int t = threadIdx.x, warp = t >> 5, lane = t & 31;
    const int grp = warp >> 2, wg = warp & 3;
    const int lr4 = lane >> 2, cq = lane & 3;
    const int m0 = blockIdx.x * 64, rl = wg * 16 + lr4;
    const uint32_t xs_b = (uint32_t)__cvta_generic_to_shared(&xs[0][0]);
    const uint32_t ws_b = (uint32_t)__cvta_generic_to_shared(&ws[0][0]);

    float acc[8][4];
#pragma unroll
    for (int n = 0; n < 8; n++) acc[n][0] = acc[n][1] = acc[n][2] = acc[n][3] = 0.f;

    auto issue = [&](int kc, int st) {
        if (t < 256) {
            int r = t >> 2, ch = t & 3;
            cp16(xs_b + (uint32_t)(st * 64 * XS + r * XS + ch * 4) * 4,
                 x + (size_t)(m0 + r) * EMB_DIM + kc * 16 + ch * 4);
        }
#pragma unroll
        for (int i = 0; i < 2; i++) {
            int c = i * 384 + t, row = c >> 2, ch = c & 3;
            cp16(ws_b + (uint32_t)(st * 192 * WS + row * WS + ch * 4) * 4,
                 g_Wt + (size_t)row * 1024 + kc * 16 + ch * 4);
        }
        CP_COMMIT();
    };

    issue(0, 0);
    for (int kc = 0; kc < 64; kc++) {
        const int st = kc & 1;
        CP_WAIT0();
        __syncthreads();
        if (kc < 63) issue(kc + 1, st ^ 1);

        uint32_t a[2][4];
#pragma unroll
        for (int kk = 0; kk < 2; kk++) {
            a[kk][0] = fu(f2tf(xs[st][rl * XS + kk * 8 + cq]));
            a[kk][1] = fu(f2tf(xs[st][(rl + 8) * XS + kk * 8 + cq]));
            a[kk][2] = fu(f2tf(xs[st][rl * XS + kk * 8 + cq + 4]));
            a[kk][3] = fu(f2tf(xs[st][(rl + 8) * XS + kk * 8 + cq + 4]));
        }
#pragma unroll
        for (int n = 0; n < 8; n++)
#pragma unroll
            for (int kk = 0; kk < 2; kk++) {
                float2 b = *reinterpret_cast<float2*>(
                    &ws[st][(grp * 64 + n * 8 + lr4) * WS + kk * 8 + 2 * cq]);
                mma8(acc[n], a[kk], fu(b.x), fu(b.y));
            }
    }

    const int bb = m0 >> 12;
    const int sbase = m0 & 4095;

#pragma unroll 1
    for (int mat = 0; mat < 3; mat++) {
        __syncthreads();
        if (grp == mat) {
            if (mat < 2) {
                const float scl = (mat == 0) ? QSCALE : 1.0f;
#pragma unroll
                for (int n = 0; n < 8; n++) {
                    int p0 = n * 8 + perm8(2 * cq), p1 = n * 8 + perm8(2 * cq + 1);
                    ts[rl * 65 + p0]       = f2tf(acc[n][0] * scl);
                    ts[rl * 65 + p1]       = f2tf(acc[n][1] * scl);
                    ts[(rl + 8) * 65 + p0] = f2tf(acc[n][2] * scl);
                    ts[(rl + 8) * 65 + p1] = f2tf(acc[n][3] * scl);
                }
            } else {
#pragma unroll
                for (int n = 0; n < 8; n++) {
                    int c0 = n * 8 + 2 * cq, c1 = c0 + 1;
                    ts[c0 * 65 + rl]     = f2tf(acc[n][0]);
                    ts[c1 * 65 + rl]     = f2tf(acc[n][1]);
                    ts[c0 * 65 + rl + 8] = f2tf(acc[n][2]);
                    ts[c1 * 65 + rl + 8] = f2tf(acc[n][3]);
                }
            }
        }
        __syncthreads();
        if (t < 256) {
            int row = t >> 2, off = (t & 3) * 16;
            float* o;
            if (mat == 0)      o = g_Q + (size_t)(m0 + row) * 64 + off;
            else if (mat == 1) o = g_K + (size_t)(m0 + row) * 64 + off;
            else               o = g_VT + ((size_t)bb * 64 + row) * SEQ + sbase + off;
#pragma unroll
            for (int i = 0; i < 4; i++) {
                float4 v = make_float4(ts[row*65+off+4*i], ts[row*65+off+4*i+1],
                                       ts[row*65+off+4*i+2], ts[row*65+off+4*i+3]);
                *reinterpret_cast<float4*>(o + 4 * i) = v;
            }
        }
    }
}

// ---------------------------------------------------------------------------
// Kernel 2: split-KV causal flash attention, 128-row Q tiles (two 64-row
// strips per warp sharing every K/V smem load). Base-2 online softmax.
// ---------------------------------------------------------------------------
#define KVS 72
#define ATTN_SMEM (2 * 2 * 64 * KVS * 4)   // 73728 B
__global__ __launch_bounds__(128, 2) void attn_kernel()
{
    extern __shared__ float sm[];
    const int t = threadIdx.x, warp = t >> 5, lane = t & 31;
    const int lr4 = lane >> 2, cq = lane & 3;
    const int rl = warp * 16 + lr4;
    const uint32_t sm_b = (uint32_t)__cvta_generic_to_shared(sm);

    // task decode: 144 tasks/batch over 32 q-tiles (128 rows), chunks <= 8 tiles
    const int tk = 575 - (int)blockIdx.x;
    const int b = tk / 144, r = tk % 144;
    int qt, ch, nc;
    if (r < 4)        { qt = r;                ch = 0;           nc = 1; }
    else if (r < 12)  { qt = 4  + (r-4)/2;     ch = (r-4)%2;     nc = 2; }
    else if (r < 24)  { qt = 8  + (r-12)/3;    ch = (r-12)%3;    nc = 3; }
    else if (r < 40)  { qt = 12 + (r-24)/4;    ch = (r-24)%4;    nc = 4; }
    else if (r < 60)  { qt = 16 + (r-40)/5;    ch = (r-40)%5;    nc = 5; }
    else if (r < 84)  { qt = 20 + (r-60)/6;    ch = (r-60)%6;    nc = 6; }
    else if (r < 112) { qt = 24 + (r-84)/7;    ch = (r-84)%7;    nc = 7; }
    else              { qt = 28 + (r-112)/8;   ch = (r-112)%8;   nc = 8; }
    const int T = 2 * qt + 2;
    const int js = (ch * T) / nc, je = ((ch + 1) * T) / nc;
    const int q0 = qt * 128;

    // Q fragments, both strips (tf32, scaled, pair-permuted)
    uint32_t aq0[8][4], aq1[8][4];
    {
        const float* Q0 = g_Q + (size_t)(b * SEQ + q0 + rl) * 64;
        const float* Q1 = Q0 + 64 * 64;
#pragma unroll
        for (int kk = 0; kk < 8; kk++) {
            float2 v0 = *reinterpret_cast<const float2*>(Q0 + kk * 8 + 2 * cq);
            float2 v1 = *reinterpret_cast<const float2*>(Q0 + 8 * 64 + kk * 8 + 2 * cq);
            aq0[kk][0] = fu(v0.x); aq0[kk][2] = fu(v0.y);
            aq0[kk][1] = fu(v1.x); aq0[kk][3] = fu(v1.y);
            float2 w0 = *reinterpret_cast<const float2*>(Q1 + kk * 8 + 2 * cq);
            float2 w1 = *reinterpret_cast<const float2*>(Q1 + 8 * 64 + kk * 8 + 2 * cq);
            aq1[kk][0] = fu(w0.x); aq1[kk][2] = fu(w0.y);
            aq1[kk][1] = fu(w1.x); aq1[kk][3] = fu(w1.y);
        }
    }

    auto issue = [&](int j, int st) {
        const float* Kg = g_K + ((size_t)b * SEQ + j * 64) * 64;
        const float* Vg = g_VT + (size_t)b * 64 * SEQ + j * 64;
        const uint32_t kb = sm_b + (uint32_t)st * 2 * 64 * KVS * 4;
        const uint32_t vb = kb + 64 * KVS * 4;
#pragma unroll
        for (int i = 0; i < 8; i++) {
            int c = i * 128 + t, rr = c >> 4, chh = c & 15;
            cp16(kb + (uint32_t)(rr * KVS + chh * 4) * 4, Kg + rr * 64 + chh * 4);
        }
#pragma unroll
        for (int i = 0; i < 8; i++) {
            int c = i * 128 + t, rr = c >> 4, chh = c & 15;
            cp16(vb + (uint32_t)(rr * KVS + chh * 4) * 4, Vg + (size_t)rr * SEQ + chh * 4);
        }
        CP_COMMIT();
    };

    float m0a = -1e30f, m0b = -1e30f, l0a = 0.f, l0b = 0.f;
    float m1a = -1e30f, m1b = -1e30f, l1a = 0.f, l1b = 0.f;
    float o0[8][4], o1[8][4];
#pragma unroll
    for (int n = 0; n < 8; n++) {
        o0[n][0] = o0[n][1] = o0[n][2] = o0[n][3] = 0.f;
        o1[n][0] = o1[n][1] = o1[n][2] = o1[n][3] = 0.f;
    }

    // online softmax for one strip: s (8x4), row-halves (ma, mb), (la, lb)
    auto softmax = [&](float (*s)[4], float& ma, float& mb, float& la, float& lb,
                       float (*o)[4]) {
        float nm0 = ma, nm1 = mb;
#pragma unroll
        for (int n = 0; n < 8; n++) {
            nm0 = fmaxf(nm0, fmaxf(s[n][0], s[n][1]));
            nm1 = fmaxf(nm1, fmaxf(s[n][2], s[n][3]));
        }
        nm0 = fmaxf(nm0, __shfl_xor_sync(0xffffffffu, nm0, 1));
        nm0 = fmaxf(nm0, __shfl_xor_sync(0xffffffffu, nm0, 2));
        nm1 = fmaxf(nm1, __shfl_xor_sync(0xffffffffu, nm1, 1));
        nm1 = fmaxf(nm1, __shfl_xor_sync(0xffffffffu, nm1, 2));
        const float sc0 = ex2(ma - nm0), sc1 = ex2(mb - nm1);
        ma = nm0; mb = nm1;
        float sum0 = 0.f, sum1 = 0.f;
#pragma unroll
        for (int n = 0; n < 8; n++) {
            float p0 = ex2(s[n][0] - nm0);
            float p1 = ex2(s[n][1] - nm0);
            float p2 = ex2(s[n][2] - nm1);
            float p3 = ex2(s[n][3] - nm1);
            sum0 += p0 + p1; sum1 += p2 + p3;
            s[n][0] = f2tf(p0); s[n][1] = f2tf(p1);
            s[n][2] = f2tf(p2); s[n][3] = f2tf(p3);
        }
        sum0 += __shfl_xor_sync(0xffffffffu, sum0, 1);
        sum0 += __shfl_xor_sync(0xffffffffu, sum0, 2);
        sum1 += __shfl_xor_sync(0xffffffffu, sum1, 1);
        sum1 += __shfl_xor_sync(0xffffffffu, sum1, 2);
        la = la * sc0 + sum0;
        lb = lb * sc1 + sum1;
#pragma unroll
        for (int n = 0; n < 8; n++) {
            o[n][0] *= sc0; o[n][1] *= sc0; o[n][2] *= sc1; o[n][3] *= sc1;
        }
    };

    issue(js, 0);
    for (int j = js; j < je; j++) {
        const int st = (j - js) & 1;
        CP_WAIT0();
        __syncthreads();
        if (j < je - 1) issue(j + 1, st ^ 1);
        const float* ks = sm + st * 2 * 64 * KVS;
        const float* vs = ks + 64 * KVS;

        const bool do0 = (j != 2 * qt + 1);   // strip0 fully masked on last tile

        float s0[8][4], s1[8][4];
#pragma unroll
        for (int n = 0; n < 8; n++) {
            s0[n][0] = s0[n][1] = s0[n][2] = s0[n][3] = 0.f;
            s1[n][0] = s1[n][1] = s1[n][2] = s1[n][3] = 0.f;
        }
        if (do0) {
#pragma unroll
            for (int n = 0; n < 8; n++)
#pragma unroll
                for (int kk = 0; kk < 8; kk++) {
                    float2 bb = *reinterpret_cast<const float2*>(
                        &ks[(n * 8 + lr4) * KVS + kk * 8 + 2 * cq]);
                    uint32_t b0 = fu(bb.x), b1 = fu(bb.y);
                    mma8(s0[n], aq0[kk], b0, b1);
                    mma8(s1[n], aq1[kk], b0, b1);
                }
        } else {
#pragma unroll
            for (int n = 0; n < 8; n++)
#pragma unroll
                for (int kk = 0; kk < 8; kk++) {
                    float2 bb = *reinterpret_cast<const float2*>(
                        &ks[(n * 8 + lr4) * KVS + kk * 8 + 2 * cq]);
                    mma8(s1[n], aq1[kk], fu(bb.x), fu(bb.y));
                }
        }

        if (j == 2 * qt) {        // strip0 diagonal tile
#pragma unroll
            for (int n = 0; n < 8; n++) {
                int c0 = n * 8 + 2 * cq;
                if (c0     > rl)     s0[n][0] = -1e30f;
                if (c0 + 1 > rl)     s0[n][1] = -1e30f;
                if (c0     > rl + 8) s0[n][2] = -1e30f;
                if (c0 + 1 > rl + 8) s0[n][3] = -1e30f;
            }
        }
        if (j == 2 * qt + 1) {    // strip1 diagonal tile
#pragma unroll
            for (int n = 0; n < 8; n++) {
                int c0 = n * 8 + 2 * cq;
                if (c0     > rl)     s1[n][0] = -1e30f;
                if (c0 + 1 > rl)     s1[n][1] = -1e30f;
                if (c0     > rl + 8) s1[n][2] = -1e30f;
                if (c0 + 1 > rl + 8) s1[n][3] = -1e30f;
            }
        }

        if (do0) softmax(s0, m0a, m0b, l0a, l0b, o0);
        softmax(s1, m1a, m1b, l1a, l1b, o1);

        // O += P @ V (shuffle-free A repack; shared V b-frags)
        if (do0) {
#pragma unroll
            for (int tt = 0; tt < 8; tt++) {
                uint32_t a0[4] = { fu(s0[tt][0]), fu(s0[tt][2]), fu(s0[tt][1]), fu(s0[tt][3]) };
                uint32_t a1[4] = { fu(s1[tt][0]), fu(s1[tt][2]), fu(s1[tt][1]), fu(s1[tt][3]) };
#pragma unroll
                for (int n = 0; n < 8; n++) {
                    float2 bb = *reinterpret_cast<const float2*>(
                        &vs[(n * 8 + lr4) * KVS + tt * 8 + 2 * cq]);
                    uint32_t b0 = fu(bb.x), b1 = fu(bb.y);
                    mma8(o0[n], a0, b0, b1);
                    mma8(o1[n], a1, b0, b1);
                }
            }
        } else {
#pragma unroll
            for (int tt = 0; tt < 8; tt++) {
                uint32_t a1[4] = { fu(s1[tt][0]), fu(s1[tt][2]), fu(s1[tt][1]), fu(s1[tt][3]) };
#pragma unroll
                for (int n = 0; n < 8; n++) {
                    float2 bb = *reinterpret_cast<const float2*>(
                        &vs[(n * 8 + lr4) * KVS + tt * 8 + 2 * cq]);
                    mma8(o1[n], a1, fu(bb.x), fu(bb.y));
                }
            }
        }
    }

    // write partials (both strips)
    const int slot = (b * 32 + qt) * 8 + ch;
    float* po = g_po + (size_t)slot * 8192;
#pragma unroll
    for (int n = 0; n < 8; n++) {
        int c = n * 8 + 2 * cq;
        *reinterpret_cast<float2*>(po + rl * 64 + c)        = make_float2(o0[n][0], o0[n][1]);
        *reinterpret_cast<float2*>(po + (rl + 8) * 64 + c)  = make_float2(o0[n][2], o0[n][3]);
        *reinterpret_cast<float2*>(po + (rl + 64) * 64 + c) = make_float2(o1[n][0], o1[n][1]);
        *reinterpret_cast<float2*>(po + (rl + 72) * 64 + c) = make_float2(o1[n][2], o1[n][3]);
    }
    if (cq == 0) {
        g_pm[slot * 128 + rl]      = m0a;  g_pl[slot * 128 + rl]      = l0a;
        g_pm[slot * 128 + rl + 8]  = m0b;  g_pl[slot * 128 + rl + 8]  = l0b;
        g_pm[slot * 128 + rl + 64] = m1a;  g_pl[slot * 128 + rl + 64] = l1a;
        g_pm[slot * 128 + rl + 72] = m1b;  g_pl[slot * 128 + rl + 72] = l1b;
    }
}

// ---------------------------------------------------------------------------
// Kernel 3: combine partials -> final output (base-2 weights).
// ---------------------------------------------------------------------------
__global__ __launch_bounds__(256) void combine_kernel(float* __restrict__ out)
{
    const int idx = blockIdx.x * 256 + threadIdx.x;
    const int row = idx >> 4, c4 = (idx & 15) * 4;
    const int b = row >> 12, s = row & 4095;
    const int qt = s >> 7, r128 = s & 127;
    const int nc = (qt >> 2) + 1;
    const int base = (b * 32 + qt) * 8;

    float mv[8];
    float M = -1e30f;
#pragma unroll
    for (int c = 0; c < 8; c++) {
        if (c < nc) {
            mv[c] = g_pm[(base + c) * 128 + r128];
            M = fmaxf(M, mv[c]);
        }
    }
    float4 acc = make_float4(0.f, 0.f, 0.f, 0.f);
    float l = 0.f;
#pragma unroll
    for (int c = 0; c < 8; c++) {
        if (c < nc) {
            float w = ex2(mv[c] - M);
            const float4 o = *reinterpret_cast<const float4*>(
                g_po + (size_t)(base + c) * 8192 + r128 * 64 + c4);
            acc.x += w * o.x; acc.y += w * o.y; acc.z += w * o.z; acc.w += w * o.w;
            l += w * g_pl[(base + c) * 128 + r128];
        }
    }
    const float inv = 1.f / l;
    acc.x *= inv; acc.y *= inv; acc.z *= inv; acc.w *= inv;
    *reinterpret_cast<float4*>(out + (size_t)row * 64 + c4) = acc;
}

extern "C" void kernel_launch(void* const* d_in, const int* in_sizes, int n_in,
                              void* d_out, int out_size) {
    const float* x  = (const float*)d_in[0];
    const float* Wq = (const float*)d_in[1];
    const float* Wk = (const float*)d_in[2];
    const float* Wv = (const float*)d_in[3];
    float* out = (float*)d_out;

    w_prep_kernel<<<dim3(16, 3), 256>>>(Wq, Wk, Wv);
    qkv_proj_kernel<<<MTOT / 64, 384>>>(x);
    cudaFuncSetAttribute(attn_kernel, cudaFuncAttributeMaxDynamicSharedMemorySize, ATTN_SMEM);
    attn_kernel<<<576, 128, ATTN_SMEM>>>();
    combine_kernel<<<1024, 256>>>(out);
}

// round 8
// speedup vs baseline: 3.0143x; 1.4739x over previous
#include <cuda_runtime.h>
#include <cuda_fp16.h>
#include <cstdint>

#define HEAD_DIM 64
#define EMB_DIM 1024
#define BATCH 4
#define SEQ 4096
#define MTOT (BATCH*SEQ)

// Q pre-scale: (1/sqrt(64)) * log2(e)  -> softmax computed base-2
#define QSCALE 0.18033688011112042f

// fp16 scratch. Q,K: [m][64], head dims pair-permuted within 16-groups (p16:
// logical {2c,2c+1,2c+8,2c+9} stored adjacent -> fragment pair = one 8B load).
// VT: [b][dim][s], key index p16-permuted within 16-groups.
__device__ __half g_Q[(size_t)MTOT * 64];
__device__ __half g_K[(size_t)MTOT * 64];
__device__ __half g_VT[(size_t)BATCH * 64 * SEQ];
__device__ __half g_Wt[3 * 64 * 1024];   // [n][k] W^T rows Q|K|V, k p16-permuted

// split-KV partial scratch: slot = ((b*32 + qtile128)*8 + chunk)
__device__ float g_po[(size_t)1024 * 128 * 64];
__device__ float g_pm[1024 * 128];
__device__ float g_pl[1024 * 128];

__device__ __forceinline__ uint32_t fu(float f) { return __float_as_uint(f); }
__device__ __forceinline__ float ex2(float x) {
    float r; asm("ex2.approx.f32 %0, %1;" : "=f"(r) : "f"(x)); return r;
}
__device__ __forceinline__ uint32_t pack2(float lo, float hi) {
    __half2 h = __floats2half2_rn(lo, hi);
    return *reinterpret_cast<uint32_t*>(&h);
}

// fp16 mma m16n8k16, fp32 accum
__device__ __forceinline__ void mma16(float* c, const uint32_t* a, uint32_t b0, uint32_t b1) {
    asm volatile(
        "mma.sync.aligned.m16n8k16.row.col.f32.f16.f16.f32 "
        "{%0,%1,%2,%3}, {%4,%5,%6,%7}, {%8,%9}, {%0,%1,%2,%3};"
        : "+f"(c[0]), "+f"(c[1]), "+f"(c[2]), "+f"(c[3])
        : "r"(a[0]), "r"(a[1]), "r"(a[2]), "r"(a[3]), "r"(b0), "r"(b1));
}

__device__ __forceinline__ void cp16(uint32_t dst, const void* src) {
    asm volatile("cp.async.cg.shared.global [%0], [%1], 16;" :: "r"(dst), "l"(src));
}
#define CP_COMMIT() asm volatile("cp.async.commit_group;")
#define CP_WAIT0()  asm volatile("cp.async.wait_group 0;")

// pair-permutation within 16-group: logical j -> phys
__device__ __forceinline__ int p16(int j) {
    return ((j & 7) >> 1) * 4 + (j & 1) + ((j >> 3) << 1);
}
__device__ __forceinline__ int p16pos(int c) { return (c & ~15) | p16(c & 15); }

// ---------------------------------------------------------------------------
// Kernel 0: transpose W to [n][k] half, k p16-permuted.
// ---------------------------------------------------------------------------
__global__ void w_prep_kernel(const float* __restrict__ Wq,
                              const float* __restrict__ Wk,
                              const float* __restrict__ Wv) {
    __shared__ float ts[64][65];
    const float* W = (blockIdx.y == 0) ? Wq : (blockIdx.y == 1) ? Wk : Wv;
    const int kt = blockIdx.x;
    const int t = threadIdx.x;   // 256 threads
    {
        int r = t >> 2, c4 = (t & 3) * 16;
        const float* src = W + (size_t)(kt * 64 + r) * 64 + c4;
#pragma unroll
        for (int i = 0; i < 4; i++) {
            const float4 v = *reinterpret_cast<const float4*>(src + 4 * i);
            ts[r][c4 + 4*i + 0] = v.x; ts[r][c4 + 4*i + 1] = v.y;
            ts[r][c4 + 4*i + 2] = v.z; ts[r][c4 + 4*i + 3] = v.w;
        }
    }
    __syncthreads();
    __half* out = g_Wt + (size_t)blockIdx.y * 64 * 1024;
#pragma unroll
    for (int i = 0; i < 16; i++) {
        int idx = i * 256 + t, n = idx >> 6, r = idx & 63;
        int rp = (r & ~15) | p16(r & 15);
        out[(size_t)n * 1024 + kt * 64 + rp] = __float2half_rn(ts[r][n]);
    }
}

// ---------------------------------------------------------------------------
// Kernel 1: fused QKV projection (fp16 mma), 384 threads: warps 0-3 Q,
// 4-7 K, 8-11 V. x tile (fp32) shared; converted to half at fragment load.
// ---------------------------------------------------------------------------
#define XS 24
__global__ __launch_bounds__(384, 2) void qkv_proj_kernel(const float* __restrict__ x)
{
    __shared__ __align__(16) float xs[2][64 * XS];        // raw fp32 x tiles
    __shared__ __align__(16) __half ws[2][192 * 16];      // half W^T tiles
    __shared__ __align__(16) __half hts[64 * 72];         // epilogue staging
    const int t = threadIdx.x, warp = t >> 5, lane = t & 31;
    const int grp = warp >> 2, wg = warp & 3;
    const int lr4 = lane >> 2, cq = lane & 3;
    const int m0 = blockIdx.x * 64, rl = wg * 16 + lr4;
    const uint32_t xs_b = (uint32_t)__cvta_generic_to_shared(&xs[0][0]);
    const uint32_t ws_b = (uint32_t)__cvta_generic_to_shared(&ws[0][0]);

    float acc[8][4];
#pragma unroll
    for (int n = 0; n < 8; n++) acc[n][0] = acc[n][1] = acc[n][2] = acc[n][3] = 0.f;

    auto issue = [&](int kc, int st) {
        if (t < 256) {   // x tile: 64 rows x 16 floats
            int r = t >> 2, ch = t & 3;
            cp16(xs_b + (uint32_t)(st * 64 * XS + r * XS + ch * 4) * 4,
                 x + (size_t)(m0 + r) * EMB_DIM + kc * 16 + ch * 4);
        }
        {   // W tiles: 192 rows x 16 halves (32B) = 384 chunks
            int row = t >> 1, ch = t & 1;
            cp16(ws_b + (uint32_t)(st * 192 * 16 + row * 16 + ch * 8) * 2,
                 g_Wt + (size_t)row * 1024 + kc * 16 + ch * 8);
        }
        CP_COMMIT();
    };

    issue(0, 0);
    for (int kc = 0; kc < 64; kc++) {
        const int st = kc & 1;
        CP_WAIT0();
        __syncthreads();
        if (kc < 63) issue(kc + 1, st ^ 1);

        // A fragments: fp32 smem -> half2 packs
        uint32_t a[4];
        {
            const float2 lo0 = *reinterpret_cast<const float2*>(&xs[st][rl * XS + 2 * cq]);
            const float2 lo1 = *reinterpret_cast<const float2*>(&xs[st][(rl + 8) * XS + 2 * cq]);
            const float2 hi0 = *reinterpret_cast<const float2*>(&xs[st][rl * XS + 2 * cq + 8]);
            const float2 hi1 = *reinterpret_cast<const float2*>(&xs[st][(rl + 8) * XS + 2 * cq + 8]);
            a[0] = pack2(lo0.x, lo0.y);
            a[1] = pack2(lo1.x, lo1.y);
            a[2] = pack2(hi0.x, hi0.y);
            a[3] = pack2(hi1.x, hi1.y);
        }
#pragma unroll
        for (int n = 0; n < 8; n++) {
            const uint2 bb = *reinterpret_cast<const uint2*>(
                &ws[st][(grp * 64 + n * 8 + lr4) * 16 + 4 * cq]);
            mma16(acc[n], a, bb.x, bb.y);
        }
    }

    const int bb = m0 >> 12;
    const int sbase = m0 & 4095;

    // Epilogue: three staged passes, half stores
#pragma unroll 1
    for (int mat = 0; mat < 3; mat++) {
        __syncthreads();
        if (grp == mat) {
            if (mat < 2) {
                const float scl = (mat == 0) ? QSCALE : 1.0f;
#pragma unroll
                for (int n = 0; n < 8; n++) {
                    int c0 = n * 8 + 2 * cq;
                    int q0p = p16pos(c0), q1p = p16pos(c0 + 1);
                    hts[rl * 72 + q0p]       = __float2half_rn(acc[n][0] * scl);
                    hts[rl * 72 + q1p]       = __float2half_rn(acc[n][1] * scl);
                    hts[(rl + 8) * 72 + q0p] = __float2half_rn(acc[n][2] * scl);
                    hts[(rl + 8) * 72 + q1p] = __float2half_rn(acc[n][3] * scl);
                }
            } else {   // V: transposed [dim][key], key p16-permuted
                const int kp0 = p16pos(rl), kp8 = p16pos(rl + 8);
#pragma unroll
                for (int n = 0; n < 8; n++) {
                    int c0 = n * 8 + 2 * cq, c1 = c0 + 1;
                    hts[c0 * 72 + kp0] = __float2half_rn(acc[n][0]);
                    hts[c1 * 72 + kp0] = __float2half_rn(acc[n][1]);
                    hts[c0 * 72 + kp8] = __float2half_rn(acc[n][2]);
                    hts[c1 * 72 + kp8] = __float2half_rn(acc[n][3]);
                }
            }
        }
        __syncthreads();
        // 64 rows x 8 x 16B segments = 512 tasks
#pragma unroll
        for (int i = 0; i < 2; i++) {
            int id = i * 384 + t;
            if (id < 512) {
                int row = id >> 3, seg = id & 7;
                uint4 v = *reinterpret_cast<const uint4*>(hts + row * 72 + seg * 8);
                __half* o;
                if (mat == 0)      o = g_Q + (size_t)(m0 + row) * 64 + seg * 8;
                else if (mat == 1) o = g_K + (size_t)(m0 + row) * 64 + seg * 8;
                else               o = g_VT + ((size_t)bb * 64 + row) * SEQ + sbase + seg * 8;
                *reinterpret_cast<uint4*>(o) = v;
            }
        }
    }
}

// ---------------------------------------------------------------------------
// Kernel 2: split-KV causal flash attention, fp16 mma, 128-row Q tiles
// (two strips share all K/V loads). Base-2 online softmax.
// ---------------------------------------------------------------------------
#define KS_H 80                    // smem row stride in halves (160 B)
#define KV_TILE (64 * KS_H * 2)    // 10240 B per tile
#define ATTN_SMEM (4 * KV_TILE)    // 40960 B
__global__ __launch_bounds__(128, 2) void attn_kernel()
{
    extern __shared__ char smc[];
    const __half* base = reinterpret_cast<const __half*>(smc);
    const int t = threadIdx.x, warp = t >> 5, lane = t & 31;
    const int lr4 = lane >> 2, cq = lane & 3;
    const int rl = warp * 16 + lr4;
    const uint32_t sm_b = (uint32_t)__cvta_generic_to_shared(smc);

    // task decode: 144 tasks/batch over 32 q-tiles (128 rows), chunks <= 8 tiles
    const int tk = 575 - (int)blockIdx.x;
    const int b = tk / 144, r = tk % 144;
    int qt, ch, nc;
    if (r < 4)        { qt = r;                ch = 0;           nc = 1; }
    else if (r < 12)  { qt = 4  + (r-4)/2;     ch = (r-4)%2;     nc = 2; }
    else if (r < 24)  { qt = 8  + (r-12)/3;    ch = (r-12)%3;    nc = 3; }
    else if (r < 40)  { qt = 12 + (r-24)/4;    ch = (r-24)%4;    nc = 4; }
    else if (r < 60)  { qt = 16 + (r-40)/5;    ch = (r-40)%5;    nc = 5; }
    else if (r < 84)  { qt = 20 + (r-60)/6;    ch = (r-60)%6;    nc = 6; }
    else if (r < 112) { qt = 24 + (r-84)/7;    ch = (r-84)%7;    nc = 7; }
    else              { qt = 28 + (r-112)/8;   ch = (r-112)%8;   nc = 8; }
    const int T = 2 * qt + 2;
    const int js = (ch * T) / nc, je = ((ch + 1) * T) / nc;
    const int q0 = qt * 128;

    // Q fragments, both strips (half, p16 dims): one LDG.64 per (row, chunk)
    uint32_t aq0[4][4], aq1[4][4];
    {
        const __half* Q0 = g_Q + ((size_t)(b * SEQ + q0) + rl) * 64;
        const __half* Q1 = Q0 + (size_t)64 * 64;
#pragma unroll
        for (int kk = 0; kk < 4; kk++) {
            uint2 v0 = *reinterpret_cast<const uint2*>(Q0 + kk * 16 + 4 * cq);
            uint2 v1 = *reinterpret_cast<const uint2*>(Q0 + 8 * 64 + kk * 16 + 4 * cq);
            aq0[kk][0] = v0.x; aq0[kk][1] = v1.x; aq0[kk][2] = v0.y; aq0[kk][3] = v1.y;
            uint2 w0 = *reinterpret_cast<const uint2*>(Q1 + kk * 16 + 4 * cq);
            uint2 w1 = *reinterpret_cast<const uint2*>(Q1 + 8 * 64 + kk * 16 + 4 * cq);
            aq1[kk][0] = w0.x; aq1[kk][1] = w1.x; aq1[kk][2] = w0.y; aq1[kk][3] = w1.y;
        }
    }

    auto issue = [&](int j, int st) {
        const __half* Kg = g_K + ((size_t)b * SEQ + j * 64) * 64;
        const __half* Vg = g_VT + (size_t)b * 64 * SEQ + j * 64;
        const uint32_t kb = sm_b + (uint32_t)st * 2 * KV_TILE;
        const uint32_t vb = kb + KV_TILE;
#pragma unroll
        for (int i = 0; i < 4; i++) {   // K: 64 rows x 8 chunks
            int c = i * 128 + t, rr = c >> 3, chh = c & 7;
            cp16(kb + (uint32_t)(rr * 160 + chh * 16), Kg + rr * 64 + chh * 8);
        }
#pragma unroll
        for (int i = 0; i < 4; i++) {   // V
            int c = i * 128 + t, rr = c >> 3, chh = c & 7;
            cp16(vb + (uint32_t)(rr * 160 + chh * 16), Vg + (size_t)rr * SEQ + chh * 8);
        }
        CP_COMMIT();
    };

    float m0a = -1e30f, m0b = -1e30f, l0a = 0.f, l0b = 0.f;
    float m1a = -1e30f, m1b = -1e30f, l1a = 0.f, l1b = 0.f;
    float o0[8][4], o1[8][4];
#pragma unroll
    for (int n = 0; n < 8; n++) {
        o0[n][0] = o0[n][1] = o0[n][2] = o0[n][3] = 0.f;
        o1[n][0] = o1[n][1] = o1[n][2] = o1[n][3] = 0.f;
    }

    auto softmax = [&](float (*s)[4], float& ma, float& mb, float& la, float& lb,
                       float (*o)[4]) {
        float nm0 = ma, nm1 = mb;
#pragma unroll
        for (int n = 0; n < 8; n++) {
            nm0 = fmaxf(nm0, fmaxf(s[n][0], s[n][1]));
            nm1 = fmaxf(nm1, fmaxf(s[n][2], s[n][3]));
        }
        nm0 = fmaxf(nm0, __shfl_xor_sync(0xffffffffu, nm0, 1));
        nm0 = fmaxf(nm0, __shfl_xor_sync(0xffffffffu, nm0, 2));
        nm1 = fmaxf(nm1, __shfl_xor_sync(0xffffffffu, nm1, 1));
        nm1 = fmaxf(nm1, __shfl_xor_sync(0xffffffffu, nm1, 2));
        const float sc0 = ex2(ma - nm0), sc1 = ex2(mb - nm1);
        ma = nm0; mb = nm1;
        float sum0 = 0.f, sum1 = 0.f;
#pragma unroll
        for (int n = 0; n < 8; n++) {
            float p0 = ex2(s[n][0] - nm0);
            float p1 = ex2(s[n][1] - nm0);
            float p2 = ex2(s[n][2] - nm1);
            float p3 = ex2(s[n][3] - nm1);
            sum0 += p0 + p1; sum1 += p2 + p3;
            s[n][0] = p0; s[n][1] = p1; s[n][2] = p2; s[n][3] = p3;
        }
        sum0 += __shfl_xor_sync(0xffffffffu, sum0, 1);
        sum0 += __shfl_xor_sync(0xffffffffu, sum0, 2);
        sum1 += __shfl_xor_sync(0xffffffffu, sum1, 1);
        sum1 += __shfl_xor_sync(0xffffffffu, sum1, 2);
        la = la * sc0 + sum0;
        lb = lb * sc1 + sum1;
#pragma unroll
        for (int n = 0; n < 8; n++) {
            o[n][0] *= sc0; o[n][1] *= sc0; o[n][2] *= sc1; o[n][3] *= sc1;
        }
    };

    issue(js, 0);
    for (int j = js; j < je; j++) {
        const int st = (j - js) & 1;
        CP_WAIT0();
        __syncthreads();
        if (j < je - 1) issue(j + 1, st ^ 1);
        const __half* ks = base + (size_t)st * 2 * 64 * KS_H;
        const __half* vs = ks + 64 * KS_H;

        const bool do0 = (j != 2 * qt + 1);

        float s0[8][4], s1[8][4];
#pragma unroll
        for (int n = 0; n < 8; n++) {
            s0[n][0] = s0[n][1] = s0[n][2] = s0[n][3] = 0.f;
            s1[n][0] = s1[n][1] = s1[n][2] = s1[n][3] = 0.f;
        }
        if (do0) {
#pragma unroll
            for (int n = 0; n < 8; n++)
#pragma unroll
                for (int kk = 0; kk < 4; kk++) {
                    const uint2 bb = *reinterpret_cast<const uint2*>(
                        ks + (n * 8 + lr4) * KS_H + kk * 16 + 4 * cq);
                    mma16(s0[n], aq0[kk], bb.x, bb.y);
                    mma16(s1[n], aq1[kk], bb.x, bb.y);
                }
        } else {
#pragma unroll
            for (int n = 0; n < 8; n++)
#pragma unroll
                for (int kk = 0; kk < 4; kk++) {
                    const uint2 bb = *reinterpret_cast<const uint2*>(
                        ks + (n * 8 + lr4) * KS_H + kk * 16 + 4 * cq);
                    mma16(s1[n], aq1[kk], bb.x, bb.y);
                }
        }

        if (j == 2 * qt) {
#pragma unroll
            for (int n = 0; n < 8; n++) {
                int c0 = n * 8 + 2 * cq;
                if (c0     > rl)     s0[n][0] = -1e30f;
                if (c0 + 1 > rl)     s0[n][1] = -1e30f;
                if (c0     > rl + 8) s0[n][2] = -1e30f;
                if (c0 + 1 > rl + 8) s0[n][3] = -1e30f;
            }
        }
        if (j == 2 * qt + 1) {
#pragma unroll
            for (int n = 0; n < 8; n++) {
                int c0 = n * 8 + 2 * cq;
                if (c0     > rl)     s1[n][0] = -1e30f;
                if (c0 + 1 > rl)     s1[n][1] = -1e30f;
                if (c0     > rl + 8) s1[n][2] = -1e30f;
                if (c0 + 1 > rl + 8) s1[n][3] = -1e30f;
            }
        }

        if (do0) softmax(s0, m0a, m0b, l0a, l0b, o0);
        softmax(s1, m1a, m1b, l1a, l1b, o1);

        // P -> fp16 A fragments (pure packing, no shuffles)
        uint32_t pa0[4][4], pa1[4][4];
#pragma unroll
        for (int tt = 0; tt < 4; tt++) {
            if (do0) {
                pa0[tt][0] = pack2(s0[2*tt][0],   s0[2*tt][1]);
                pa0[tt][1] = pack2(s0[2*tt][2],   s0[2*tt][3]);
                pa0[tt][2] = pack2(s0[2*tt+1][0], s0[2*tt+1][1]);
                pa0[tt][3] = pack2(s0[2*tt+1][2], s0[2*tt+1][3]);
            }
            pa1[tt][0] = pack2(s1[2*tt][0],   s1[2*tt][1]);
            pa1[tt][1] = pack2(s1[2*tt][2],   s1[2*tt][3]);
            pa1[tt][2] = pack2(s1[2*tt+1][0], s1[2*tt+1][1]);
            pa1[tt][3] = pack2(s1[2*tt+1][2], s1[2*tt+1][3]);
        }

        if (do0) {
#pragma unroll
            for (int n = 0; n < 8; n++)
#pragma unroll
                for (int tt = 0; tt < 4; tt++) {
                    const uint2 bb = *reinterpret_cast<const uint2*>(
                        vs + (n * 8 + lr4) * KS_H + tt * 16 + 4 * cq);
                    mma16(o0[n], pa0[tt], bb.x, bb.y);
                    mma16(o1[n], pa1[tt], bb.x, bb.y);
                }
        } else {
#pragma unroll
            for (int n = 0; n < 8; n++)
#pragma unroll
                for (int tt = 0; tt < 4; tt++) {
                    const uint2 bb = *reinterpret_cast<const uint2*>(
                        vs + (n * 8 + lr4) * KS_H + tt * 16 + 4 * cq);
                    mma16(o1[n], pa1[tt], bb.x, bb.y);
                }
        }
    }

    // write partials (fp32)
    const int slot = (b * 32 + qt) * 8 + ch;
    float* po = g_po + (size_t)slot * 8192;
#pragma unroll
    for (int n = 0; n < 8; n++) {
        int c = n * 8 + 2 * cq;
        *reinterpret_cast<float2*>(po + rl * 64 + c)        = make_float2(o0[n][0], o0[n][1]);
        *reinterpret_cast<float2*>(po + (rl + 8) * 64 + c)  = make_float2(o0[n][2], o0[n][3]);
        *reinterpret_cast<float2*>(po + (rl + 64) * 64 + c) = make_float2(o1[n][0], o1[n][1]);
        *reinterpret_cast<float2*>(po + (rl + 72) * 64 + c) = make_float2(o1[n][2], o1[n][3]);
    }
    if (cq == 0) {
        g_pm[slot * 128 + rl]      = m0a;  g_pl[slot * 128 + rl]      = l0a;
        g_pm[slot * 128 + rl + 8]  = m0b;  g_pl[slot * 128 + rl + 8]  = l0b;
        g_pm[slot * 128 + rl + 64] = m1a;  g_pl[slot * 128 + rl + 64] = l1a;
        g_pm[slot * 128 + rl + 72] = m1b;  g_pl[slot * 128 + rl + 72] = l1b;
    }
}

// ---------------------------------------------------------------------------
// Kernel 3: combine partials -> final output (base-2 weights).
// ---------------------------------------------------------------------------
__global__ __launch_bounds__(256) void combine_kernel(float* __restrict__ out)
{
    const int idx = blockIdx.x * 256 + threadIdx.x;
    const int row = idx >> 4, c4 = (idx & 15) * 4;
    const int b = row >> 12, s = row & 4095;
    const int qt = s >> 7, r128 = s & 127;
    const int nc = (qt >> 2) + 1;
    const int base = (b * 32 + qt) * 8;

    float mv[8];
    float M = -1e30f;
#pragma unroll
    for (int c = 0; c < 8; c++) {
        if (c < nc) {
            mv[c] = g_pm[(base + c) * 128 + r128];
            M = fmaxf(M, mv[c]);
        }
    }
    float4 acc = make_float4(0.f, 0.f, 0.f, 0.f);
    float l = 0.f;
#pragma unroll
    for (int c = 0; c < 8; c++) {
        if (c < nc) {
            float w = ex2(mv[c] - M);
            const float4 o = *reinterpret_cast<const float4*>(
                g_po + (size_t)(base + c) * 8192 + r128 * 64 + c4);
            acc.x += w * o.x; acc.y += w * o.y; acc.z += w * o.z; acc.w += w * o.w;
            l += w * g_pl[(base + c) * 128 + r128];
        }
    }
    const float inv = 1.f / l;
    acc.x *= inv; acc.y *= inv; acc.z *= inv; acc.w *= inv;
    *reinterpret_cast<float4*>(out + (size_t)row * 64 + c4) = acc;
}

extern "C" void kernel_launch(void* const* d_in, const int* in_sizes, int n_in,
                              void* d_out, int out_size) {
    const float* x  = (const float*)d_in[0];
    const float* Wq = (const float*)d_in[1];
    const float* Wk = (const float*)d_in[2];
    const float* Wv = (const float*)d_in[3];
    float* out = (float*)d_out;

    w_prep_kernel<<<dim3(16, 3), 256>>>(Wq, Wk, Wv);
    qkv_proj_kernel<<<MTOT / 64, 384>>>(x);
    cudaFuncSetAttribute(attn_kernel, cudaFuncAttributeMaxDynamicSharedMemorySize, ATTN_SMEM);
    attn_kernel<<<576, 128, ATTN_SMEM>>>();
    combine_kernel<<<1024, 256>>>(out);
}